// round 14
// baseline (speedup 1.0000x reference)
#include <cuda_runtime.h>
#include <cuda_bf16.h>
#include <cstdint>
#include <math.h>

// Problem constants
#define BB   4
#define SS   2048
#define DD   1024
#define HH   16
#define DHH  64
#define FFD  4096
#define MM   (BB*SS)      // 8192 rows

typedef __nv_bfloat16 bf16;

// ---------------------------------------------------------------------------
// Scratch (static __device__ — no allocations allowed)
// ---------------------------------------------------------------------------
__device__ bf16  g_ln [MM*DD];
__device__ float g_qkv[MM*3*DD];     // fp32 bits, tf32-rounded (attention input)
__device__ bf16  g_att[MM*DD];
__device__ bf16  g_ctx[MM*DD];
__device__ float g_x1 [MM*DD];
__device__ float g_xs [MM*DD];
__device__ float g_u  [MM*DD];
__device__ float g_al [MM*DD];
__device__ float g_be [MM*DD];
__device__ float g_gg [MM*DD];
__device__ float g_x2 [MM*DD];
__device__ bf16  g_ff [MM*FFD];
// Pre-converted bf16 weights
__device__ bf16 g_w_qkv[3*DD*DD];
__device__ bf16 g_w_out[DD*DD];
__device__ bf16 g_w_u [DD*DD];
__device__ bf16 g_w_a [DD*DD];
__device__ bf16 g_w_b [DD*DD];
__device__ bf16 g_w_g [DD*DD];
__device__ bf16 g_w_f1[FFD*DD];
__device__ bf16 g_w_f2[DD*FFD];

// ---------------------------------------------------------------------------
// Helpers
// ---------------------------------------------------------------------------
__device__ __forceinline__ uint32_t smem_u32(const void* p) {
    uint32_t a;
    asm("{ .reg .u64 t; cvta.to.shared.u64 t, %1; cvt.u32.u64 %0, t; }" : "=r"(a) : "l"(p));
    return a;
}
__device__ __forceinline__ uint32_t f2tf32(float f) {
    uint32_t u;
    asm("cvt.rna.tf32.f32 %0, %1;" : "=r"(u) : "f"(f));
    return u;
}
__device__ __forceinline__ uint32_t pack_bf2(float lo, float hi) {
    __nv_bfloat162 h = __floats2bfloat162_rn(lo, hi);
    return *reinterpret_cast<uint32_t*>(&h);
}
__device__ __forceinline__ uint32_t lds_u32(uint32_t addr) {
    uint32_t v;
    asm volatile("ld.shared.b32 %0, [%1];" : "=r"(v) : "r"(addr));
    return v;
}
__device__ __forceinline__ void cp16(uint32_t dst, const void* src) {
    asm volatile("cp.async.cg.shared.global [%0], [%1], 16;" :: "r"(dst), "l"(src));
}
#define CP_COMMIT() asm volatile("cp.async.commit_group;" ::: "memory")
__device__ __forceinline__ void cp_wait1() { asm volatile("cp.async.wait_group 1;" ::: "memory"); }
__device__ __forceinline__ void cp_wait0() { asm volatile("cp.async.wait_group 0;" ::: "memory"); }
#define SWZ128(off) ((off) ^ (((off) >> 3) & 0x70))

__device__ __forceinline__ void mma_bf16(float* c, const uint32_t* a, uint32_t b0, uint32_t b1) {
    asm volatile("mma.sync.aligned.m16n8k16.row.col.f32.bf16.bf16.f32 "
        "{%0,%1,%2,%3}, {%4,%5,%6,%7}, {%8,%9}, {%0,%1,%2,%3};"
        : "+f"(c[0]), "+f"(c[1]), "+f"(c[2]), "+f"(c[3])
        : "r"(a[0]), "r"(a[1]), "r"(a[2]), "r"(a[3]), "r"(b0), "r"(b1));
}
__device__ __forceinline__ void mma_tf32(float* c, const uint32_t* a, uint32_t b0, uint32_t b1) {
    asm volatile("mma.sync.aligned.m16n8k8.row.col.f32.tf32.tf32.f32 "
        "{%0,%1,%2,%3}, {%4,%5,%6,%7}, {%8,%9}, {%0,%1,%2,%3};"
        : "+f"(c[0]), "+f"(c[1]), "+f"(c[2]), "+f"(c[3])
        : "r"(a[0]), "r"(a[1]), "r"(a[2]), "r"(a[3]), "r"(b0), "r"(b1));
}

// ---------------------------------------------------------------------------
// Fused fp32->bf16 conversion of all 8 weight tensors (one launch).
// ---------------------------------------------------------------------------
#define USEG (DD*DD/8)
__global__ void __launch_bounds__(256) cvt_all_kernel(
    const float* __restrict__ s_qkv, const float* __restrict__ s_out,
    const float* __restrict__ s_u,   const float* __restrict__ s_a,
    const float* __restrict__ s_b,   const float* __restrict__ s_g,
    const float* __restrict__ s_f1,  const float* __restrict__ s_f2,
    bf16* d_qkv, bf16* d_out, bf16* d_u, bf16* d_a,
    bf16* d_b, bf16* d_g, bf16* d_f1, bf16* d_f2)
{
    int i = blockIdx.x * blockDim.x + threadIdx.x;
    const float* src; bf16* dst; int off;
    if      (i <  3 * USEG) { src = s_qkv; dst = d_qkv; off = i; }
    else if (i <  4 * USEG) { src = s_out; dst = d_out; off = i -  3 * USEG; }
    else if (i <  5 * USEG) { src = s_u;   dst = d_u;   off = i -  4 * USEG; }
    else if (i <  6 * USEG) { src = s_a;   dst = d_a;   off = i -  5 * USEG; }
    else if (i <  7 * USEG) { src = s_b;   dst = d_b;   off = i -  6 * USEG; }
    else if (i <  8 * USEG) { src = s_g;   dst = d_g;   off = i -  7 * USEG; }
    else if (i < 12 * USEG) { src = s_f1;  dst = d_f1;  off = i -  8 * USEG; }
    else                    { src = s_f2;  dst = d_f2;  off = i - 12 * USEG; }
    float4 v0 = ((const float4*)src)[2 * off];
    float4 v1 = ((const float4*)src)[2 * off + 1];
    uint4 o;
    o.x = pack_bf2(v0.x, v0.y);
    o.y = pack_bf2(v0.z, v0.w);
    o.z = pack_bf2(v1.x, v1.y);
    o.w = pack_bf2(v1.z, v1.w);
    ((uint4*)dst)[off] = o;
}

// ---------------------------------------------------------------------------
// Shared bf16 GEMM mainloop (proven scalar-LDS fragment loads).
// ---------------------------------------------------------------------------
#define STAGE_BYTES 32768
#define NSTAGE 3
#define GEMM_SMEM   (NSTAGE * STAGE_BYTES + 1024)

__device__ __forceinline__ void bf16_mainloop(
    const bf16* __restrict__ Abase, const bf16* __restrict__ Wbase,
    int K, uint32_t base, float acc[4][8][4])
{
    const int tid = threadIdx.x;
    const int lane = tid & 31;
    const int wid = tid >> 5;
    const int gID = lane >> 2, tig = lane & 3;
    const int wm = (wid & 1) * 64;
    const int wn = (wid >> 1) * 64;

    const uint32_t gOff0 = (uint32_t)((tid >> 3) * K + (tid & 7) * 8);
    const uint32_t gStep = (uint32_t)(16 * K);
    const uint32_t sOff0 = SWZ128((uint32_t)((tid >> 3) * 128 + (tid & 7) * 16));

    const uint32_t rowA0 = (uint32_t)((wm + gID) * 128);
    const uint32_t rowB0 = (uint32_t)((wn + gID) * 128);
    const uint32_t xmask = (uint32_t)(gID << 4);

    const int niter = K / 64;

    #pragma unroll
    for (int p = 0; p < 2; p++) {
        uint32_t st = base + p * STAGE_BYTES;
        const bf16* As = Abase + p * 64;
        const bf16* Ws = Wbase + p * 64;
        #pragma unroll
        for (int i = 0; i < 8; i++) cp16(st + sOff0 + i * 2048, As + gOff0 + i * gStep);
        #pragma unroll
        for (int i = 0; i < 8; i++) cp16(st + 16384 + sOff0 + i * 2048, Ws + gOff0 + i * gStep);
        CP_COMMIT();
    }

    int stage = 0;
    for (int it = 0; it < niter; it++) {
        if (it + 1 < niter) cp_wait1(); else cp_wait0();
        __syncthreads();

        if (it + 2 < niter) {
            int ns = stage + 2; if (ns >= NSTAGE) ns -= NSTAGE;
            uint32_t st = base + ns * STAGE_BYTES;
            const bf16* As = Abase + (it + 2) * 64;
            const bf16* Ws = Wbase + (it + 2) * 64;
            #pragma unroll
            for (int i = 0; i < 8; i++) cp16(st + sOff0 + i * 2048, As + gOff0 + i * gStep);
            #pragma unroll
            for (int i = 0; i < 8; i++) cp16(st + 16384 + sOff0 + i * 2048, Ws + gOff0 + i * gStep);
            CP_COMMIT();
        }

        uint32_t sA = base + stage * STAGE_BYTES;
        uint32_t sB = sA + 16384;

        uint32_t af[2][4][4];
        uint32_t bfr[2][8][2];
        {
            uint32_t x0 = ((uint32_t)(tig * 4)) ^ xmask;
            uint32_t x1 = x0 ^ 16u;
            #pragma unroll
            for (int mi = 0; mi < 4; mi++) {
                af[0][mi][0] = lds_u32(sA + rowA0 + mi * 2048 + x0);
                af[0][mi][1] = lds_u32(sA + rowA0 + mi * 2048 + 1024 + x0);
                af[0][mi][2] = lds_u32(sA + rowA0 + mi * 2048 + x1);
                af[0][mi][3] = lds_u32(sA + rowA0 + mi * 2048 + 1024 + x1);
            }
            #pragma unroll
            for (int ni = 0; ni < 8; ni++) {
                bfr[0][ni][0] = lds_u32(sB + rowB0 + ni * 1024 + x0);
                bfr[0][ni][1] = lds_u32(sB + rowB0 + ni * 1024 + x1);
            }
        }
        #pragma unroll
        for (int s = 0; s < 4; s++) {
            int cur = s & 1, nxt = cur ^ 1;
            if (s < 3) {
                uint32_t x0 = ((uint32_t)((s + 1) * 32 + tig * 4)) ^ xmask;
                uint32_t x1 = x0 ^ 16u;
                #pragma unroll
                for (int mi = 0; mi < 4; mi++) {
                    af[nxt][mi][0] = lds_u32(sA + rowA0 + mi * 2048 + x0);
                    af[nxt][mi][1] = lds_u32(sA + rowA0 + mi * 2048 + 1024 + x0);
                    af[nxt][mi][2] = lds_u32(sA + rowA0 + mi * 2048 + x1);
                    af[nxt][mi][3] = lds_u32(sA + rowA0 + mi * 2048 + 1024 + x1);
                }
                #pragma unroll
                for (int ni = 0; ni < 8; ni++) {
                    bfr[nxt][ni][0] = lds_u32(sB + rowB0 + ni * 1024 + x0);
                    bfr[nxt][ni][1] = lds_u32(sB + rowB0 + ni * 1024 + x1);
                }
            }
            #pragma unroll
            for (int ni = 0; ni < 8; ni++)
                #pragma unroll
                for (int mi = 0; mi < 4; mi++)
                    mma_bf16(acc[mi][ni], af[cur][mi], bfr[cur][ni][0], bfr[cur][ni][1]);
        }

        stage++; if (stage >= NSTAGE) stage = 0;
    }
}

// ---------------------------------------------------------------------------
// Standard GEMM kernel with templated epilogue.
// EPI: 0=none 1=gelu 2=sigmoid 3=softplus 4=C=v+res 5=dual(Cb16=v, C2=v+res)
// CB16: C stored bf16.  RT32: C stored fp32 but tf32-rounded (feeds attention).
// ---------------------------------------------------------------------------
template<int EPI, bool CB16, bool RT32>
__global__ void __launch_bounds__(128, 2) gemm_tc(
    const bf16* __restrict__ A, const bf16* __restrict__ W,
    const float* __restrict__ bias, void* __restrict__ Cv,
    float* __restrict__ C2, const float* __restrict__ res,
    int M, int N, int K)
{
    extern __shared__ char dsm[];
    uint32_t raw = smem_u32(dsm);
    uint32_t base = (raw + 1023u) & ~1023u;

    float acc[4][8][4];
    #pragma unroll
    for (int mi = 0; mi < 4; mi++)
        #pragma unroll
        for (int ni = 0; ni < 8; ni++)
            #pragma unroll
            for (int j = 0; j < 4; j++) acc[mi][ni][j] = 0.f;

    bf16_mainloop(A + (size_t)(blockIdx.y * 128) * K,
                  W + (size_t)(blockIdx.x * 128) * K, K, base, acc);

    int tid = threadIdx.x;
    int wid = tid >> 5, lane = tid & 31;
    int gID = lane >> 2, tig = lane & 3;
    float* Cf = (float*)Cv;
    bf16*  Cb = (bf16*)Cv;
    int row0 = blockIdx.y * 128 + (wid & 1) * 64 + gID;
    int col0 = blockIdx.x * 128 + (wid >> 1) * 64;
    #pragma unroll
    for (int mi = 0; mi < 4; mi++) {
        #pragma unroll
        for (int half = 0; half < 2; half++) {
            int r = row0 + mi * 16 + half * 8;
            size_t rbase = (size_t)r * N;
            #pragma unroll
            for (int ni = 0; ni < 8; ni++) {
                int c = col0 + ni * 8 + 2 * tig;
                float v0 = acc[mi][ni][half * 2 + 0] + bias[c];
                float v1 = acc[mi][ni][half * 2 + 1] + bias[c + 1];
                if (EPI == 1) {
                    v0 = 0.5f * v0 * (1.0f + erff(v0 * 0.70710678118654752f));
                    v1 = 0.5f * v1 * (1.0f + erff(v1 * 0.70710678118654752f));
                } else if (EPI == 2) {
                    v0 = 1.0f / (1.0f + expf(-v0));
                    v1 = 1.0f / (1.0f + expf(-v1));
                } else if (EPI == 3) {
                    v0 = (v0 > 0.f) ? (v0 + log1pf(expf(-v0))) : log1pf(expf(v0));
                    v1 = (v1 > 0.f) ? (v1 + log1pf(expf(-v1))) : log1pf(expf(v1));
                }
                if (EPI == 4) {
                    float2 r2 = *(const float2*)(res + rbase + c);
                    *(float2*)(Cf + rbase + c) = make_float2(v0 + r2.x, v1 + r2.y);
                } else if (EPI == 5) {
                    float2 r2 = *(const float2*)(res + rbase + c);
                    *(uint32_t*)(Cb + rbase + c) = pack_bf2(v0, v1);
                    *(float2*)(C2 + rbase + c) = make_float2(v0 + r2.x, v1 + r2.y);
                } else if (CB16) {
                    *(uint32_t*)(Cb + rbase + c) = pack_bf2(v0, v1);
                } else if (RT32) {
                    *(float2*)(Cf + rbase + c) = make_float2(
                        __uint_as_float(f2tf32(v0)), __uint_as_float(f2tf32(v1)));
                } else {
                    *(float2*)(Cf + rbase + c) = make_float2(v0, v1);
                }
            }
        }
    }
}

// ---------------------------------------------------------------------------
// Batched INL controller GEMM: blockIdx.z selects weight/bias/output/act.
// ---------------------------------------------------------------------------
__global__ void __launch_bounds__(128, 2) gemm_inl(
    const bf16* __restrict__ A,
    const bf16* __restrict__ W0, const bf16* __restrict__ W1,
    const bf16* __restrict__ W2, const bf16* __restrict__ W3,
    const float* __restrict__ b0, const float* __restrict__ b1,
    const float* __restrict__ b2, const float* __restrict__ b3,
    float* __restrict__ C0, float* __restrict__ C1,
    float* __restrict__ C2o, float* __restrict__ C3,
    int M, int N, int K)
{
    extern __shared__ char dsm[];
    uint32_t raw = smem_u32(dsm);
    uint32_t base = (raw + 1023u) & ~1023u;

    int z = blockIdx.z;
    const bf16*  W    = (z == 0) ? W0 : (z == 1) ? W1 : (z == 2) ? W2 : W3;
    const float* bias = (z == 0) ? b0 : (z == 1) ? b1 : (z == 2) ? b2 : b3;
    float*       C    = (z == 0) ? C0 : (z == 1) ? C1 : (z == 2) ? C2o : C3;

    float acc[4][8][4];
    #pragma unroll
    for (int mi = 0; mi < 4; mi++)
        #pragma unroll
        for (int ni = 0; ni < 8; ni++)
            #pragma unroll
            for (int j = 0; j < 4; j++) acc[mi][ni][j] = 0.f;

    bf16_mainloop(A + (size_t)(blockIdx.y * 128) * K,
                  W + (size_t)(blockIdx.x * 128) * K, K, base, acc);

    int tid = threadIdx.x;
    int wid = tid >> 5, lane = tid & 31;
    int gID = lane >> 2, tig = lane & 3;
    int row0 = blockIdx.y * 128 + (wid & 1) * 64 + gID;
    int col0 = blockIdx.x * 128 + (wid >> 1) * 64;
    #pragma unroll
    for (int mi = 0; mi < 4; mi++) {
        #pragma unroll
        for (int half = 0; half < 2; half++) {
            int r = row0 + mi * 16 + half * 8;
            size_t rbase = (size_t)r * N;
            #pragma unroll
            for (int ni = 0; ni < 8; ni++) {
                int c = col0 + ni * 8 + 2 * tig;
                float v0 = acc[mi][ni][half * 2 + 0] + bias[c];
                float v1 = acc[mi][ni][half * 2 + 1] + bias[c + 1];
                if (z == 2) {
                    v0 = (v0 > 0.f) ? (v0 + log1pf(expf(-v0))) : log1pf(expf(v0));
                    v1 = (v1 > 0.f) ? (v1 + log1pf(expf(-v1))) : log1pf(expf(v1));
                } else if (z != 0) {
                    v0 = 1.0f / (1.0f + expf(-v0));
                    v1 = 1.0f / (1.0f + expf(-v1));
                }
                *(float2*)(C + rbase + c) = make_float2(v0, v1);
            }
        }
    }
}

// ---------------------------------------------------------------------------
// Tensor-core causal flash attention with double-buffered K/V cp.async pipeline.
// qkv already tf32-rounded; Q scale 2^-3 exact. Longest Q-tiles scheduled first.
// Smem: K0,V0,K1,V1,P — 5 * 64 * PITCH floats.
// ---------------------------------------------------------------------------
#define PITCH 72
#define KVT (64 * PITCH)
#define ATT_SMEM (5 * KVT * 4)

__global__ void __launch_bounds__(128) attn_tc_kernel(
    const float* __restrict__ qkv, bf16* __restrict__ out)
{
    extern __shared__ float sm[];
    float* Ps = sm + 4 * KVT;
    uint32_t sb = smem_u32(sm);

    int tid = threadIdx.x;
    int wid = tid >> 5, lane = tid & 31;
    int gID = lane >> 2, tig = lane & 3;
    int b = blockIdx.y >> 4, h = blockIdx.y & 15;
    // Longest-first scheduling: high q0 blocks issued first
    int qb = (int)gridDim.x - 1 - (int)blockIdx.x;
    int q0 = qb * 64;
    const float scale = 0.125f;

    // Per-thread K/V staging offsets (row = f>>4, col = (f&15)*4)
    uint32_t kvso[8];
    size_t   kvgo[8];
    #pragma unroll
    for (int i = 0; i < 8; i++) {
        int f = tid + i * 128;
        int r = f >> 4;
        int c = (f & 15) * 4;
        kvso[i] = (uint32_t)((r * PITCH + c) * 4);
        kvgo[i] = (size_t)(b * SS + r) * (3 * DD) + h * DHH + c;
    }

    int nt = qb + 1;
    // Prologue: issue K/V tile 0 into buffer 0
    {
        size_t koff = (size_t)0 * (3 * DD);
        #pragma unroll
        for (int i = 0; i < 8; i++) {
            cp16(sb + kvso[i], qkv + kvgo[i] + koff + DD);
            cp16(sb + KVT * 4 + kvso[i], qkv + kvgo[i] + koff + 2 * DD);
        }
        CP_COMMIT();
    }

    // Load Q tile (already tf32-rounded; *2^-3 exact) into Ps staging
    #pragma unroll
    for (int i = 0; i < 8; i++) {
        int f = tid + i * 128;
        int r = f >> 4;
        int c = (f & 15) * 4;
        float4 v = *(const float4*)&qkv[(size_t)(b * SS + q0 + r) * (3 * DD) + h * DHH + c];
        *(float4*)&Ps[r * PITCH + c] =
            make_float4(v.x * scale, v.y * scale, v.z * scale, v.w * scale);
    }
    __syncthreads();

    int rA = wid * 16 + gID;
    uint32_t qf[8][4];
    #pragma unroll
    for (int s = 0; s < 8; s++) {
        qf[s][0] = __float_as_uint(Ps[rA * PITCH + 8 * s + tig]);
        qf[s][1] = __float_as_uint(Ps[(rA + 8) * PITCH + 8 * s + tig]);
        qf[s][2] = __float_as_uint(Ps[rA * PITCH + 8 * s + tig + 4]);
        qf[s][3] = __float_as_uint(Ps[(rA + 8) * PITCH + 8 * s + tig + 4]);
    }

    float of[8][4];
    #pragma unroll
    for (int ni = 0; ni < 8; ni++)
        #pragma unroll
        for (int j = 0; j < 4; j++) of[ni][j] = 0.f;
    float m0 = -1e30f, m1 = -1e30f, l0 = 0.f, l1 = 0.f;

    for (int jt = 0; jt < nt; jt++) {
        int buf = jt & 1;
        // Prefetch next tile into alternate buffer, then wait for current
        if (jt + 1 < nt) {
            uint32_t dst = sb + (uint32_t)((buf ^ 1) * 2) * (KVT * 4);
            size_t koff = (size_t)((jt + 1) * 64) * (3 * DD);
            #pragma unroll
            for (int i = 0; i < 8; i++) {
                cp16(dst + kvso[i], qkv + kvgo[i] + koff + DD);
                cp16(dst + KVT * 4 + kvso[i], qkv + kvgo[i] + koff + 2 * DD);
            }
            CP_COMMIT();
            cp_wait1();
        } else {
            cp_wait0();
        }
        __syncthreads();

        const float* Ks = sm + buf * 2 * KVT;
        const float* Vs = Ks + KVT;

        float sc[8][4];
        #pragma unroll
        for (int ni = 0; ni < 8; ni++)
            #pragma unroll
            for (int j = 0; j < 4; j++) sc[ni][j] = 0.f;
        #pragma unroll
        for (int s = 0; s < 8; s++) {
            #pragma unroll
            for (int ni = 0; ni < 8; ni++) {
                uint32_t b0 = __float_as_uint(Ks[(ni * 8 + gID) * PITCH + 8 * s + tig]);
                uint32_t b1 = __float_as_uint(Ks[(ni * 8 + gID) * PITCH + 8 * s + tig + 4]);
                mma_tf32(sc[ni], qf[s], b0, b1);
            }
        }

        if (jt == nt - 1) {
            #pragma unroll
            for (int ni = 0; ni < 8; ni++) {
                int ct = ni * 8 + 2 * tig;
                if (ct > rA)         sc[ni][0] = -1e30f;
                if (ct + 1 > rA)     sc[ni][1] = -1e30f;
                if (ct > rA + 8)     sc[ni][2] = -1e30f;
                if (ct + 1 > rA + 8) sc[ni][3] = -1e30f;
            }
        }

        float mx0 = -1e30f, mx1 = -1e30f;
        #pragma unroll
        for (int ni = 0; ni < 8; ni++) {
            mx0 = fmaxf(mx0, fmaxf(sc[ni][0], sc[ni][1]));
            mx1 = fmaxf(mx1, fmaxf(sc[ni][2], sc[ni][3]));
        }
        mx0 = fmaxf(mx0, __shfl_xor_sync(0xffffffffu, mx0, 1));
        mx0 = fmaxf(mx0, __shfl_xor_sync(0xffffffffu, mx0, 2));
        mx1 = fmaxf(mx1, __shfl_xor_sync(0xffffffffu, mx1, 1));
        mx1 = fmaxf(mx1, __shfl_xor_sync(0xffffffffu, mx1, 2));
        float mn0 = fmaxf(m0, mx0), mn1 = fmaxf(m1, mx1);
        float rs0 = expf(m0 - mn0), rs1 = expf(m1 - mn1);
        m0 = mn0; m1 = mn1;

        float sum0 = 0.f, sum1 = 0.f;
        #pragma unroll
        for (int ni = 0; ni < 8; ni++) {
            sc[ni][0] = expf(sc[ni][0] - mn0);
            sc[ni][1] = expf(sc[ni][1] - mn0);
            sc[ni][2] = expf(sc[ni][2] - mn1);
            sc[ni][3] = expf(sc[ni][3] - mn1);
            sum0 += sc[ni][0] + sc[ni][1];
            sum1 += sc[ni][2] + sc[ni][3];
        }
        sum0 += __shfl_xor_sync(0xffffffffu, sum0, 1);
        sum0 += __shfl_xor_sync(0xffffffffu, sum0, 2);
        sum1 += __shfl_xor_sync(0xffffffffu, sum1, 1);
        sum1 += __shfl_xor_sync(0xffffffffu, sum1, 2);
        l0 = l0 * rs0 + sum0;
        l1 = l1 * rs1 + sum1;

        #pragma unroll
        for (int ni = 0; ni < 8; ni++) {
            of[ni][0] *= rs0; of[ni][1] *= rs0;
            of[ni][2] *= rs1; of[ni][3] *= rs1;
        }

        #pragma unroll
        for (int ni = 0; ni < 8; ni++) {
            uint32_t* p0 = (uint32_t*)&Ps[rA * PITCH + ni * 8 + 2 * tig];
            p0[0] = f2tf32(sc[ni][0]); p0[1] = f2tf32(sc[ni][1]);
            uint32_t* p1 = (uint32_t*)&Ps[(rA + 8) * PITCH + ni * 8 + 2 * tig];
            p1[0] = f2tf32(sc[ni][2]); p1[1] = f2tf32(sc[ni][3]);
        }
        __syncwarp();

        #pragma unroll
        for (int s = 0; s < 8; s++) {
            uint32_t pa[4];
            pa[0] = __float_as_uint(Ps[rA * PITCH + 8 * s + tig]);
            pa[1] = __float_as_uint(Ps[(rA + 8) * PITCH + 8 * s + tig]);
            pa[2] = __float_as_uint(Ps[rA * PITCH + 8 * s + tig + 4]);
            pa[3] = __float_as_uint(Ps[(rA + 8) * PITCH + 8 * s + tig + 4]);
            #pragma unroll
            for (int ni = 0; ni < 8; ni++) {
                uint32_t b0 = __float_as_uint(Vs[(8 * s + tig) * PITCH + ni * 8 + gID]);
                uint32_t b1 = __float_as_uint(Vs[(8 * s + tig + 4) * PITCH + ni * 8 + gID]);
                mma_tf32(of[ni], pa, b0, b1);
            }
        }
        __syncthreads();   // all reads of this buffer done before it is rewritten
    }

    float inv0 = 1.0f / l0, inv1 = 1.0f / l1;
    size_t row0 = (size_t)(b * SS + q0 + rA);
    #pragma unroll
    for (int ni = 0; ni < 8; ni++) {
        int d = h * DHH + ni * 8 + 2 * tig;
        *(uint32_t*)&out[row0 * DD + d]       = pack_bf2(of[ni][0] * inv0, of[ni][1] * inv0);
        *(uint32_t*)&out[(row0 + 8) * DD + d] = pack_bf2(of[ni][2] * inv1, of[ni][3] * inv1);
    }
}

// ---------------------------------------------------------------------------
// LayerNorm: one block per row. BF16OUT when the output feeds a GEMM.
// ---------------------------------------------------------------------------
template<bool BF16OUT>
__global__ void __launch_bounds__(256) ln_kernel(
    const float* __restrict__ x, const float* __restrict__ w,
    const float* __restrict__ b, void* __restrict__ outv)
{
    int row = blockIdx.x;
    int tid = threadIdx.x;
    const float4* xr = (const float4*)(x + (size_t)row * DD);
    float4 v = xr[tid];

    __shared__ float red[8];
    float s = v.x + v.y + v.z + v.w;
    #pragma unroll
    for (int o = 16; o > 0; o >>= 1) s += __shfl_xor_sync(0xffffffffu, s, o);
    if ((tid & 31) == 0) red[tid >> 5] = s;
    __syncthreads();
    __shared__ float s_mean, s_rstd;
    if (tid == 0) {
        float t = 0.f;
        #pragma unroll
        for (int i = 0; i < 8; i++) t += red[i];
        s_mean = t * (1.0f / DD);
    }
    __syncthreads();
    float mean = s_mean;
    float d0 = v.x - mean, d1 = v.y - mean, d2 = v.z - mean, d3 = v.w - mean;
    float sq = d0*d0 + d1*d1 + d2*d2 + d3*d3;
    #pragma unroll
    for (int o = 16; o > 0; o >>= 1) sq += __shfl_xor_sync(0xffffffffu, sq, o);
    __syncthreads();
    if ((tid & 31) == 0) red[tid >> 5] = sq;
    __syncthreads();
    if (tid == 0) {
        float t = 0.f;
        #pragma unroll
        for (int i = 0; i < 8; i++) t += red[i];
        s_rstd = rsqrtf(t * (1.0f / DD) + 1e-5f);
    }
    __syncthreads();
    float rstd = s_rstd;
    float4 wv = ((const float4*)w)[tid];
    float4 bv = ((const float4*)b)[tid];
    float o0 = d0 * rstd * wv.x + bv.x;
    float o1 = d1 * rstd * wv.y + bv.y;
    float o2 = d2 * rstd * wv.z + bv.z;
    float o3 = d3 * rstd * wv.w + bv.w;
    if (BF16OUT) {
        bf16* out = (bf16*)outv;
        uint2 o4 = make_uint2(pack_bf2(o0, o1), pack_bf2(o2, o3));
        *(uint2*)(out + (size_t)row * DD + tid * 4) = o4;
    } else {
        float* out = (float*)outv;
        ((float4*)(out + (size_t)row * DD))[tid] = make_float4(o0, o1, o2, o3);
    }
}

// ---------------------------------------------------------------------------
// INL integrator: elementwise, 5 unrolled steps (DT=0.1, TARGET=0)
// ---------------------------------------------------------------------------
__global__ void __launch_bounds__(256) integrate_kernel(
    const float* __restrict__ xs0, const float* __restrict__ u,
    const float* __restrict__ al, const float* __restrict__ be,
    const float* __restrict__ gg, const float* __restrict__ x1,
    float* __restrict__ x2)
{
    int i = blockIdx.x * blockDim.x + threadIdx.x;
    float4 xs = ((const float4*)xs0)[i];
    float4 uu = ((const float4*)u)[i];
    float4 aa = ((const float4*)al)[i];
    float4 bb = ((const float4*)be)[i];
    float4 g4 = ((const float4*)gg)[i];
    float4 r1 = ((const float4*)x1)[i];
    float4 vs = make_float4(0.f, 0.f, 0.f, 0.f);
    const float DT = 0.1f;
    #pragma unroll
    for (int t = 0; t < 5; t++) {
        vs.x += DT * (-aa.x * xs.x - bb.x * vs.x + uu.x);  xs.x += DT * g4.x * vs.x;
        vs.y += DT * (-aa.y * xs.y - bb.y * vs.y + uu.y);  xs.y += DT * g4.y * vs.y;
        vs.z += DT * (-aa.z * xs.z - bb.z * vs.z + uu.z);  xs.z += DT * g4.z * vs.z;
        vs.w += DT * (-aa.w * xs.w - bb.w * vs.w + uu.w);  xs.w += DT * g4.w * vs.w;
    }
    float4 o4 = make_float4(r1.x + xs.x, r1.y + xs.y, r1.z + xs.z, r1.w + xs.w);
    ((float4*)x2)[i] = o4;
}

// ---------------------------------------------------------------------------
// Host launcher
// ---------------------------------------------------------------------------
extern "C" void kernel_launch(void* const* d_in, const int* in_sizes, int n_in,
                              void* d_out, int out_size)
{
    const float* x          = (const float*)d_in[0];
    const float* ln_attn_w  = (const float*)d_in[1];
    const float* ln_attn_b  = (const float*)d_in[2];
    const float* attn_in_w  = (const float*)d_in[3];
    const float* attn_in_b  = (const float*)d_in[4];
    const float* attn_out_w = (const float*)d_in[5];
    const float* attn_out_b = (const float*)d_in[6];
    const float* ln1_w      = (const float*)d_in[7];
    const float* ln1_b      = (const float*)d_in[8];
    const float* ln2_w      = (const float*)d_in[9];
    const float* ln2_b      = (const float*)d_in[10];
    const float* inl_u_w    = (const float*)d_in[11];
    const float* inl_u_b    = (const float*)d_in[12];
    const float* inl_a_w    = (const float*)d_in[13];
    const float* inl_a_b    = (const float*)d_in[14];
    const float* inl_b_w    = (const float*)d_in[15];
    const float* inl_b_b    = (const float*)d_in[16];
    const float* inl_g_w    = (const float*)d_in[17];
    const float* inl_g_b    = (const float*)d_in[18];
    const float* ff1_w      = (const float*)d_in[19];
    const float* ff1_b      = (const float*)d_in[20];
    const float* ff2_w      = (const float*)d_in[21];
    const float* ff2_b      = (const float*)d_in[22];
    float* out = (float*)d_out;

    float *p_qkv, *p_x1, *p_xs, *p_u, *p_al, *p_be, *p_gg, *p_x2;
    bf16 *p_ln, *p_att, *p_ctx, *p_ff;
    bf16 *w_qkv, *w_out, *w_u, *w_a, *w_b, *w_g, *w_f1, *w_f2;
    cudaGetSymbolAddress((void**)&p_ln,  g_ln);
    cudaGetSymbolAddress((void**)&p_qkv, g_qkv);
    cudaGetSymbolAddress((void**)&p_att, g_att);
    cudaGetSymbolAddress((void**)&p_ctx, g_ctx);
    cudaGetSymbolAddress((void**)&p_x1,  g_x1);
    cudaGetSymbolAddress((void**)&p_xs,  g_xs);
    cudaGetSymbolAddress((void**)&p_u,   g_u);
    cudaGetSymbolAddress((void**)&p_al,  g_al);
    cudaGetSymbolAddress((void**)&p_be,  g_be);
    cudaGetSymbolAddress((void**)&p_gg,  g_gg);
    cudaGetSymbolAddress((void**)&p_x2,  g_x2);
    cudaGetSymbolAddress((void**)&p_ff,  g_ff);
    cudaGetSymbolAddress((void**)&w_qkv, g_w_qkv);
    cudaGetSymbolAddress((void**)&w_out, g_w_out);
    cudaGetSymbolAddress((void**)&w_u,   g_w_u);
    cudaGetSymbolAddress((void**)&w_a,   g_w_a);
    cudaGetSymbolAddress((void**)&w_b,   g_w_b);
    cudaGetSymbolAddress((void**)&w_g,   g_w_g);
    cudaGetSymbolAddress((void**)&w_f1,  g_w_f1);
    cudaGetSymbolAddress((void**)&w_f2,  g_w_f2);

    cudaFuncSetAttribute((const void*)gemm_tc<0,false,true>,  cudaFuncAttributeMaxDynamicSharedMemorySize, GEMM_SMEM);
    cudaFuncSetAttribute((const void*)gemm_tc<1,true,false>,  cudaFuncAttributeMaxDynamicSharedMemorySize, GEMM_SMEM);
    cudaFuncSetAttribute((const void*)gemm_tc<4,false,false>, cudaFuncAttributeMaxDynamicSharedMemorySize, GEMM_SMEM);
    cudaFuncSetAttribute((const void*)gemm_tc<5,true,false>,  cudaFuncAttributeMaxDynamicSharedMemorySize, GEMM_SMEM);
    cudaFuncSetAttribute((const void*)gemm_inl,               cudaFuncAttributeMaxDynamicSharedMemorySize, GEMM_SMEM);
    cudaFuncSetAttribute((const void*)attn_tc_kernel,         cudaFuncAttributeMaxDynamicSharedMemorySize, ATT_SMEM);

    // 0. Pre-round all weights to bf16 (single launch)
    cvt_all_kernel<<<16 * USEG / 256, 256>>>(
        attn_in_w, attn_out_w, inl_u_w, inl_a_w, inl_b_w, inl_g_w, ff1_w, ff2_w,
        w_qkv, w_out, w_u, w_a, w_b, w_g, w_f1, w_f2);

    // 1. ln_attn(x) -> g_ln (bf16)
    ln_kernel<true><<<MM, 256>>>(x, ln_attn_w, ln_attn_b, p_ln);
    // 2. qkv = g_ln @ w_qkv^T + b  (fp32 bits, tf32-rounded, feeds attention)
    gemm_tc<0,false,true><<<dim3(3 * DD / 128, MM / 128), 128, GEMM_SMEM>>>(
        p_ln, w_qkv, attn_in_b, p_qkv, nullptr, nullptr, MM, 3 * DD, DD);
    // 3. causal MHA -> g_att (bf16)
    attn_tc_kernel<<<dim3(SS / 64, BB * HH), 128, ATT_SMEM>>>(p_qkv, p_att);
    // 4. ctx(bf16) = g_att @ w_out^T + b ; x1(fp32) = x + ctx
    gemm_tc<5,true,false><<<dim3(DD / 128, MM / 128), 128, GEMM_SMEM>>>(
        p_att, w_out, attn_out_b, p_ctx, p_x1, x, MM, DD, DD);
    // 5. xs = ln1(x1) (fp32, integrator input)
    ln_kernel<false><<<MM, 256>>>(p_x1, ln1_w, ln1_b, p_xs);
    // 6. INL controllers from ctx (batched: z=0..3)
    gemm_inl<<<dim3(DD / 128, MM / 128, 4), 128, GEMM_SMEM>>>(
        p_ctx, w_u, w_a, w_b, w_g,
        inl_u_b, inl_a_b, inl_b_b, inl_g_b,
        p_u, p_al, p_be, p_gg, MM, DD, DD);
    // 7. integrate -> x2 = x1 + xs_final
    integrate_kernel<<<(MM * DD / 4) / 256, 256>>>(p_xs, p_u, p_al, p_be, p_gg, p_x1, p_x2);
    // 8. ln2(x2) -> g_ln (bf16)
    ln_kernel<true><<<MM, 256>>>(p_x2, ln2_w, ln2_b, p_ln);
    // 9. ff1 + exact GELU -> g_ff (bf16)
    gemm_tc<1,true,false><<<dim3(FFD / 128, MM / 128), 128, GEMM_SMEM>>>(
        p_ln, w_f1, ff1_b, p_ff, nullptr, nullptr, MM, FFD, DD);
    // 10. out = g_ff @ w_f2^T + b + x2
    gemm_tc<4,false,false><<<dim3(DD / 128, MM / 128), 128, GEMM_SMEM>>>(
        p_ff, w_f2, ff2_b, out, nullptr, p_x2, MM, DD, FFD);
}

// round 15
// speedup vs baseline: 1.0082x; 1.0082x over previous
#include <cuda_runtime.h>
#include <cuda_bf16.h>
#include <cstdint>
#include <math.h>

// Problem constants
#define BB   4
#define SS   2048
#define DD   1024
#define HH   16
#define DHH  64
#define FFD  4096
#define MM   (BB*SS)      // 8192 rows

typedef __nv_bfloat16 bf16;

// ---------------------------------------------------------------------------
// Scratch (static __device__ — no allocations allowed)
// ---------------------------------------------------------------------------
__device__ bf16  g_ln [MM*DD];
__device__ float g_qkv[MM*3*DD];     // fp32 bits, tf32-rounded (attention input)
__device__ bf16  g_att[MM*DD];
__device__ bf16  g_ctx[MM*DD];
__device__ float g_x1 [MM*DD];
__device__ float g_xs [MM*DD];
__device__ float g_u  [MM*DD];
__device__ float g_al [MM*DD];
__device__ float g_be [MM*DD];
__device__ float g_gg [MM*DD];
__device__ float g_x2 [MM*DD];
__device__ bf16  g_ff [MM*FFD];
// Pre-converted bf16 weights
__device__ bf16 g_w_qkv[3*DD*DD];
__device__ bf16 g_w_out[DD*DD];
__device__ bf16 g_w_u [DD*DD];
__device__ bf16 g_w_a [DD*DD];
__device__ bf16 g_w_b [DD*DD];
__device__ bf16 g_w_g [DD*DD];
__device__ bf16 g_w_f1[FFD*DD];
__device__ bf16 g_w_f2[DD*FFD];

// ---------------------------------------------------------------------------
// Helpers
// ---------------------------------------------------------------------------
__device__ __forceinline__ uint32_t smem_u32(const void* p) {
    uint32_t a;
    asm("{ .reg .u64 t; cvta.to.shared.u64 t, %1; cvt.u32.u64 %0, t; }" : "=r"(a) : "l"(p));
    return a;
}
__device__ __forceinline__ uint32_t f2tf32(float f) {
    uint32_t u;
    asm("cvt.rna.tf32.f32 %0, %1;" : "=r"(u) : "f"(f));
    return u;
}
__device__ __forceinline__ uint32_t pack_bf2(float lo, float hi) {
    __nv_bfloat162 h = __floats2bfloat162_rn(lo, hi);
    return *reinterpret_cast<uint32_t*>(&h);
}
__device__ __forceinline__ uint32_t lds_u32(uint32_t addr) {
    uint32_t v;
    asm volatile("ld.shared.b32 %0, [%1];" : "=r"(v) : "r"(addr));
    return v;
}
__device__ __forceinline__ void cp16(uint32_t dst, const void* src) {
    asm volatile("cp.async.cg.shared.global [%0], [%1], 16;" :: "r"(dst), "l"(src));
}
#define CP_COMMIT() asm volatile("cp.async.commit_group;" ::: "memory")
__device__ __forceinline__ void cp_wait1() { asm volatile("cp.async.wait_group 1;" ::: "memory"); }
__device__ __forceinline__ void cp_wait0() { asm volatile("cp.async.wait_group 0;" ::: "memory"); }
#define SWZ128(off) ((off) ^ (((off) >> 3) & 0x70))

__device__ __forceinline__ void mma_bf16(float* c, const uint32_t* a, uint32_t b0, uint32_t b1) {
    asm volatile("mma.sync.aligned.m16n8k16.row.col.f32.bf16.bf16.f32 "
        "{%0,%1,%2,%3}, {%4,%5,%6,%7}, {%8,%9}, {%0,%1,%2,%3};"
        : "+f"(c[0]), "+f"(c[1]), "+f"(c[2]), "+f"(c[3])
        : "r"(a[0]), "r"(a[1]), "r"(a[2]), "r"(a[3]), "r"(b0), "r"(b1));
}
__device__ __forceinline__ void mma_tf32(float* c, const uint32_t* a, uint32_t b0, uint32_t b1) {
    asm volatile("mma.sync.aligned.m16n8k8.row.col.f32.tf32.tf32.f32 "
        "{%0,%1,%2,%3}, {%4,%5,%6,%7}, {%8,%9}, {%0,%1,%2,%3};"
        : "+f"(c[0]), "+f"(c[1]), "+f"(c[2]), "+f"(c[3])
        : "r"(a[0]), "r"(a[1]), "r"(a[2]), "r"(a[3]), "r"(b0), "r"(b1));
}

// ---------------------------------------------------------------------------
// Fused fp32->bf16 conversion of all 8 weight tensors (one launch).
// ---------------------------------------------------------------------------
#define USEG (DD*DD/8)
__global__ void __launch_bounds__(256) cvt_all_kernel(
    const float* __restrict__ s_qkv, const float* __restrict__ s_out,
    const float* __restrict__ s_u,   const float* __restrict__ s_a,
    const float* __restrict__ s_b,   const float* __restrict__ s_g,
    const float* __restrict__ s_f1,  const float* __restrict__ s_f2,
    bf16* d_qkv, bf16* d_out, bf16* d_u, bf16* d_a,
    bf16* d_b, bf16* d_g, bf16* d_f1, bf16* d_f2)
{
    int i = blockIdx.x * blockDim.x + threadIdx.x;
    const float* src; bf16* dst; int off;
    if      (i <  3 * USEG) { src = s_qkv; dst = d_qkv; off = i; }
    else if (i <  4 * USEG) { src = s_out; dst = d_out; off = i -  3 * USEG; }
    else if (i <  5 * USEG) { src = s_u;   dst = d_u;   off = i -  4 * USEG; }
    else if (i <  6 * USEG) { src = s_a;   dst = d_a;   off = i -  5 * USEG; }
    else if (i <  7 * USEG) { src = s_b;   dst = d_b;   off = i -  6 * USEG; }
    else if (i <  8 * USEG) { src = s_g;   dst = d_g;   off = i -  7 * USEG; }
    else if (i < 12 * USEG) { src = s_f1;  dst = d_f1;  off = i -  8 * USEG; }
    else                    { src = s_f2;  dst = d_f2;  off = i - 12 * USEG; }
    float4 v0 = ((const float4*)src)[2 * off];
    float4 v1 = ((const float4*)src)[2 * off + 1];
    uint4 o;
    o.x = pack_bf2(v0.x, v0.y);
    o.y = pack_bf2(v0.z, v0.w);
    o.z = pack_bf2(v1.x, v1.y);
    o.w = pack_bf2(v1.z, v1.w);
    ((uint4*)dst)[off] = o;
}

// ---------------------------------------------------------------------------
// Shared bf16 GEMM mainloop (proven scalar-LDS fragment loads).
// ---------------------------------------------------------------------------
#define STAGE_BYTES 32768
#define NSTAGE 3
#define GEMM_SMEM   (NSTAGE * STAGE_BYTES + 1024)

__device__ __forceinline__ void bf16_mainloop(
    const bf16* __restrict__ Abase, const bf16* __restrict__ Wbase,
    int K, uint32_t base, float acc[4][8][4])
{
    const int tid = threadIdx.x;
    const int lane = tid & 31;
    const int wid = tid >> 5;
    const int gID = lane >> 2, tig = lane & 3;
    const int wm = (wid & 1) * 64;
    const int wn = (wid >> 1) * 64;

    const uint32_t gOff0 = (uint32_t)((tid >> 3) * K + (tid & 7) * 8);
    const uint32_t gStep = (uint32_t)(16 * K);
    const uint32_t sOff0 = SWZ128((uint32_t)((tid >> 3) * 128 + (tid & 7) * 16));

    const uint32_t rowA0 = (uint32_t)((wm + gID) * 128);
    const uint32_t rowB0 = (uint32_t)((wn + gID) * 128);
    const uint32_t xmask = (uint32_t)(gID << 4);

    const int niter = K / 64;

    #pragma unroll
    for (int p = 0; p < 2; p++) {
        uint32_t st = base + p * STAGE_BYTES;
        const bf16* As = Abase + p * 64;
        const bf16* Ws = Wbase + p * 64;
        #pragma unroll
        for (int i = 0; i < 8; i++) cp16(st + sOff0 + i * 2048, As + gOff0 + i * gStep);
        #pragma unroll
        for (int i = 0; i < 8; i++) cp16(st + 16384 + sOff0 + i * 2048, Ws + gOff0 + i * gStep);
        CP_COMMIT();
    }

    int stage = 0;
    for (int it = 0; it < niter; it++) {
        if (it + 1 < niter) cp_wait1(); else cp_wait0();
        __syncthreads();

        if (it + 2 < niter) {
            int ns = stage + 2; if (ns >= NSTAGE) ns -= NSTAGE;
            uint32_t st = base + ns * STAGE_BYTES;
            const bf16* As = Abase + (it + 2) * 64;
            const bf16* Ws = Wbase + (it + 2) * 64;
            #pragma unroll
            for (int i = 0; i < 8; i++) cp16(st + sOff0 + i * 2048, As + gOff0 + i * gStep);
            #pragma unroll
            for (int i = 0; i < 8; i++) cp16(st + 16384 + sOff0 + i * 2048, Ws + gOff0 + i * gStep);
            CP_COMMIT();
        }

        uint32_t sA = base + stage * STAGE_BYTES;
        uint32_t sB = sA + 16384;

        uint32_t af[2][4][4];
        uint32_t bfr[2][8][2];
        {
            uint32_t x0 = ((uint32_t)(tig * 4)) ^ xmask;
            uint32_t x1 = x0 ^ 16u;
            #pragma unroll
            for (int mi = 0; mi < 4; mi++) {
                af[0][mi][0] = lds_u32(sA + rowA0 + mi * 2048 + x0);
                af[0][mi][1] = lds_u32(sA + rowA0 + mi * 2048 + 1024 + x0);
                af[0][mi][2] = lds_u32(sA + rowA0 + mi * 2048 + x1);
                af[0][mi][3] = lds_u32(sA + rowA0 + mi * 2048 + 1024 + x1);
            }
            #pragma unroll
            for (int ni = 0; ni < 8; ni++) {
                bfr[0][ni][0] = lds_u32(sB + rowB0 + ni * 1024 + x0);
                bfr[0][ni][1] = lds_u32(sB + rowB0 + ni * 1024 + x1);
            }
        }
        #pragma unroll
        for (int s = 0; s < 4; s++) {
            int cur = s & 1, nxt = cur ^ 1;
            if (s < 3) {
                uint32_t x0 = ((uint32_t)((s + 1) * 32 + tig * 4)) ^ xmask;
                uint32_t x1 = x0 ^ 16u;
                #pragma unroll
                for (int mi = 0; mi < 4; mi++) {
                    af[nxt][mi][0] = lds_u32(sA + rowA0 + mi * 2048 + x0);
                    af[nxt][mi][1] = lds_u32(sA + rowA0 + mi * 2048 + 1024 + x0);
                    af[nxt][mi][2] = lds_u32(sA + rowA0 + mi * 2048 + x1);
                    af[nxt][mi][3] = lds_u32(sA + rowA0 + mi * 2048 + 1024 + x1);
                }
                #pragma unroll
                for (int ni = 0; ni < 8; ni++) {
                    bfr[nxt][ni][0] = lds_u32(sB + rowB0 + ni * 1024 + x0);
                    bfr[nxt][ni][1] = lds_u32(sB + rowB0 + ni * 1024 + x1);
                }
            }
            #pragma unroll
            for (int ni = 0; ni < 8; ni++)
                #pragma unroll
                for (int mi = 0; mi < 4; mi++)
                    mma_bf16(acc[mi][ni], af[cur][mi], bfr[cur][ni][0], bfr[cur][ni][1]);
        }

        stage++; if (stage >= NSTAGE) stage = 0;
    }
}

// ---------------------------------------------------------------------------
// Standard GEMM kernel with templated epilogue.
// EPI: 0=none 1=gelu 2=sigmoid 3=softplus 4=C=v+res 5=dual(Cb16=v, C2=v+res)
// CB16: C stored bf16.  RT32: C stored fp32 but tf32-rounded (feeds attention).
// ---------------------------------------------------------------------------
template<int EPI, bool CB16, bool RT32>
__global__ void __launch_bounds__(128, 2) gemm_tc(
    const bf16* __restrict__ A, const bf16* __restrict__ W,
    const float* __restrict__ bias, void* __restrict__ Cv,
    float* __restrict__ C2, const float* __restrict__ res,
    int M, int N, int K)
{
    extern __shared__ char dsm[];
    uint32_t raw = smem_u32(dsm);
    uint32_t base = (raw + 1023u) & ~1023u;

    float acc[4][8][4];
    #pragma unroll
    for (int mi = 0; mi < 4; mi++)
        #pragma unroll
        for (int ni = 0; ni < 8; ni++)
            #pragma unroll
            for (int j = 0; j < 4; j++) acc[mi][ni][j] = 0.f;

    bf16_mainloop(A + (size_t)(blockIdx.y * 128) * K,
                  W + (size_t)(blockIdx.x * 128) * K, K, base, acc);

    int tid = threadIdx.x;
    int wid = tid >> 5, lane = tid & 31;
    int gID = lane >> 2, tig = lane & 3;
    float* Cf = (float*)Cv;
    bf16*  Cb = (bf16*)Cv;
    int row0 = blockIdx.y * 128 + (wid & 1) * 64 + gID;
    int col0 = blockIdx.x * 128 + (wid >> 1) * 64;
    #pragma unroll
    for (int mi = 0; mi < 4; mi++) {
        #pragma unroll
        for (int half = 0; half < 2; half++) {
            int r = row0 + mi * 16 + half * 8;
            size_t rbase = (size_t)r * N;
            #pragma unroll
            for (int ni = 0; ni < 8; ni++) {
                int c = col0 + ni * 8 + 2 * tig;
                float v0 = acc[mi][ni][half * 2 + 0] + bias[c];
                float v1 = acc[mi][ni][half * 2 + 1] + bias[c + 1];
                if (EPI == 1) {
                    v0 = 0.5f * v0 * (1.0f + erff(v0 * 0.70710678118654752f));
                    v1 = 0.5f * v1 * (1.0f + erff(v1 * 0.70710678118654752f));
                } else if (EPI == 2) {
                    v0 = 1.0f / (1.0f + expf(-v0));
                    v1 = 1.0f / (1.0f + expf(-v1));
                } else if (EPI == 3) {
                    v0 = (v0 > 0.f) ? (v0 + log1pf(expf(-v0))) : log1pf(expf(v0));
                    v1 = (v1 > 0.f) ? (v1 + log1pf(expf(-v1))) : log1pf(expf(v1));
                }
                if (EPI == 4) {
                    float2 r2 = *(const float2*)(res + rbase + c);
                    *(float2*)(Cf + rbase + c) = make_float2(v0 + r2.x, v1 + r2.y);
                } else if (EPI == 5) {
                    float2 r2 = *(const float2*)(res + rbase + c);
                    *(uint32_t*)(Cb + rbase + c) = pack_bf2(v0, v1);
                    *(float2*)(C2 + rbase + c) = make_float2(v0 + r2.x, v1 + r2.y);
                } else if (CB16) {
                    *(uint32_t*)(Cb + rbase + c) = pack_bf2(v0, v1);
                } else if (RT32) {
                    *(float2*)(Cf + rbase + c) = make_float2(
                        __uint_as_float(f2tf32(v0)), __uint_as_float(f2tf32(v1)));
                } else {
                    *(float2*)(Cf + rbase + c) = make_float2(v0, v1);
                }
            }
        }
    }
}

// ---------------------------------------------------------------------------
// Batched INL controller GEMM: blockIdx.z selects weight/bias/output/act.
// ---------------------------------------------------------------------------
__global__ void __launch_bounds__(128, 2) gemm_inl(
    const bf16* __restrict__ A,
    const bf16* __restrict__ W0, const bf16* __restrict__ W1,
    const bf16* __restrict__ W2, const bf16* __restrict__ W3,
    const float* __restrict__ b0, const float* __restrict__ b1,
    const float* __restrict__ b2, const float* __restrict__ b3,
    float* __restrict__ C0, float* __restrict__ C1,
    float* __restrict__ C2o, float* __restrict__ C3,
    int M, int N, int K)
{
    extern __shared__ char dsm[];
    uint32_t raw = smem_u32(dsm);
    uint32_t base = (raw + 1023u) & ~1023u;

    int z = blockIdx.z;
    const bf16*  W    = (z == 0) ? W0 : (z == 1) ? W1 : (z == 2) ? W2 : W3;
    const float* bias = (z == 0) ? b0 : (z == 1) ? b1 : (z == 2) ? b2 : b3;
    float*       C    = (z == 0) ? C0 : (z == 1) ? C1 : (z == 2) ? C2o : C3;

    float acc[4][8][4];
    #pragma unroll
    for (int mi = 0; mi < 4; mi++)
        #pragma unroll
        for (int ni = 0; ni < 8; ni++)
            #pragma unroll
            for (int j = 0; j < 4; j++) acc[mi][ni][j] = 0.f;

    bf16_mainloop(A + (size_t)(blockIdx.y * 128) * K,
                  W + (size_t)(blockIdx.x * 128) * K, K, base, acc);

    int tid = threadIdx.x;
    int wid = tid >> 5, lane = tid & 31;
    int gID = lane >> 2, tig = lane & 3;
    int row0 = blockIdx.y * 128 + (wid & 1) * 64 + gID;
    int col0 = blockIdx.x * 128 + (wid >> 1) * 64;
    #pragma unroll
    for (int mi = 0; mi < 4; mi++) {
        #pragma unroll
        for (int half = 0; half < 2; half++) {
            int r = row0 + mi * 16 + half * 8;
            size_t rbase = (size_t)r * N;
            #pragma unroll
            for (int ni = 0; ni < 8; ni++) {
                int c = col0 + ni * 8 + 2 * tig;
                float v0 = acc[mi][ni][half * 2 + 0] + bias[c];
                float v1 = acc[mi][ni][half * 2 + 1] + bias[c + 1];
                if (z == 2) {
                    v0 = (v0 > 0.f) ? (v0 + log1pf(expf(-v0))) : log1pf(expf(v0));
                    v1 = (v1 > 0.f) ? (v1 + log1pf(expf(-v1))) : log1pf(expf(v1));
                } else if (z != 0) {
                    v0 = 1.0f / (1.0f + expf(-v0));
                    v1 = 1.0f / (1.0f + expf(-v1));
                }
                *(float2*)(C + rbase + c) = make_float2(v0, v1);
            }
        }
    }
}

// ---------------------------------------------------------------------------
// Tensor-core causal flash attention (R13 single-buffer structure).
// qkv already tf32-rounded; Q scale 2^-3 exact. Longest Q-tiles first.
// Softmax uses __expf (fast exp) — args <= 0, rel err ~1e-6, negligible vs
// the 8e-4 operand-rounding floor.
// ---------------------------------------------------------------------------
#define PITCH 72
#define ATT_SMEM (3 * 64 * PITCH * 4)

__global__ void __launch_bounds__(128) attn_tc_kernel(
    const float* __restrict__ qkv, bf16* __restrict__ out)
{
    extern __shared__ float sm[];
    float* Ks = sm;
    float* Vs = sm + 64 * PITCH;
    float* Ps = sm + 2 * 64 * PITCH;
    uint32_t ksb = smem_u32(Ks);
    uint32_t vsb = smem_u32(Vs);

    int tid = threadIdx.x;
    int wid = tid >> 5, lane = tid & 31;
    int gID = lane >> 2, tig = lane & 3;
    int b = blockIdx.y >> 4, h = blockIdx.y & 15;
    // Longest-first scheduling
    int qb = (int)gridDim.x - 1 - (int)blockIdx.x;
    int q0 = qb * 64;
    const float scale = 0.125f;

    // Load Q tile (already tf32-rounded; *2^-3 exact) into Ps staging
    #pragma unroll
    for (int i = 0; i < 8; i++) {
        int f = tid + i * 128;
        int r = f >> 4;
        int c = (f & 15) * 4;
        float4 v = *(const float4*)&qkv[(size_t)(b * SS + q0 + r) * (3 * DD) + h * DHH + c];
        *(float4*)&Ps[r * PITCH + c] =
            make_float4(v.x * scale, v.y * scale, v.z * scale, v.w * scale);
    }
    __syncthreads();

    int rA = wid * 16 + gID;
    uint32_t qf[8][4];
    #pragma unroll
    for (int s = 0; s < 8; s++) {
        qf[s][0] = __float_as_uint(Ps[rA * PITCH + 8 * s + tig]);
        qf[s][1] = __float_as_uint(Ps[(rA + 8) * PITCH + 8 * s + tig]);
        qf[s][2] = __float_as_uint(Ps[rA * PITCH + 8 * s + tig + 4]);
        qf[s][3] = __float_as_uint(Ps[(rA + 8) * PITCH + 8 * s + tig + 4]);
    }

    float of[8][4];
    #pragma unroll
    for (int ni = 0; ni < 8; ni++)
        #pragma unroll
        for (int j = 0; j < 4; j++) of[ni][j] = 0.f;
    float m0 = -1e30f, m1 = -1e30f, l0 = 0.f, l1 = 0.f;

    int nt = qb + 1;
    for (int jt = 0; jt < nt; jt++) {
        int k0 = jt * 64;
        __syncthreads();   // prior-iteration K/V reads complete
        #pragma unroll
        for (int i = 0; i < 8; i++) {
            int f = tid + i * 128;
            int r = f >> 4;
            int c = (f & 15) * 4;
            size_t gb = (size_t)(b * SS + k0 + r) * (3 * DD) + h * DHH + c;
            uint32_t so = (uint32_t)((r * PITCH + c) * 4);
            cp16(ksb + so, qkv + gb + DD);
            cp16(vsb + so, qkv + gb + 2 * DD);
        }
        CP_COMMIT();
        cp_wait0();
        __syncthreads();

        float sc[8][4];
        #pragma unroll
        for (int ni = 0; ni < 8; ni++)
            #pragma unroll
            for (int j = 0; j < 4; j++) sc[ni][j] = 0.f;
        #pragma unroll
        for (int s = 0; s < 8; s++) {
            #pragma unroll
            for (int ni = 0; ni < 8; ni++) {
                uint32_t b0 = __float_as_uint(Ks[(ni * 8 + gID) * PITCH + 8 * s + tig]);
                uint32_t b1 = __float_as_uint(Ks[(ni * 8 + gID) * PITCH + 8 * s + tig + 4]);
                mma_tf32(sc[ni], qf[s], b0, b1);
            }
        }

        if (jt == nt - 1) {
            #pragma unroll
            for (int ni = 0; ni < 8; ni++) {
                int ct = ni * 8 + 2 * tig;
                if (ct > rA)         sc[ni][0] = -1e30f;
                if (ct + 1 > rA)     sc[ni][1] = -1e30f;
                if (ct > rA + 8)     sc[ni][2] = -1e30f;
                if (ct + 1 > rA + 8) sc[ni][3] = -1e30f;
            }
        }

        float mx0 = -1e30f, mx1 = -1e30f;
        #pragma unroll
        for (int ni = 0; ni < 8; ni++) {
            mx0 = fmaxf(mx0, fmaxf(sc[ni][0], sc[ni][1]));
            mx1 = fmaxf(mx1, fmaxf(sc[ni][2], sc[ni][3]));
        }
        mx0 = fmaxf(mx0, __shfl_xor_sync(0xffffffffu, mx0, 1));
        mx0 = fmaxf(mx0, __shfl_xor_sync(0xffffffffu, mx0, 2));
        mx1 = fmaxf(mx1, __shfl_xor_sync(0xffffffffu, mx1, 1));
        mx1 = fmaxf(mx1, __shfl_xor_sync(0xffffffffu, mx1, 2));
        float mn0 = fmaxf(m0, mx0), mn1 = fmaxf(m1, mx1);
        float rs0 = __expf(m0 - mn0), rs1 = __expf(m1 - mn1);
        m0 = mn0; m1 = mn1;

        float sum0 = 0.f, sum1 = 0.f;
        #pragma unroll
        for (int ni = 0; ni < 8; ni++) {
            sc[ni][0] = __expf(sc[ni][0] - mn0);
            sc[ni][1] = __expf(sc[ni][1] - mn0);
            sc[ni][2] = __expf(sc[ni][2] - mn1);
            sc[ni][3] = __expf(sc[ni][3] - mn1);
            sum0 += sc[ni][0] + sc[ni][1];
            sum1 += sc[ni][2] + sc[ni][3];
        }
        sum0 += __shfl_xor_sync(0xffffffffu, sum0, 1);
        sum0 += __shfl_xor_sync(0xffffffffu, sum0, 2);
        sum1 += __shfl_xor_sync(0xffffffffu, sum1, 1);
        sum1 += __shfl_xor_sync(0xffffffffu, sum1, 2);
        l0 = l0 * rs0 + sum0;
        l1 = l1 * rs1 + sum1;

        #pragma unroll
        for (int ni = 0; ni < 8; ni++) {
            of[ni][0] *= rs0; of[ni][1] *= rs0;
            of[ni][2] *= rs1; of[ni][3] *= rs1;
        }

        #pragma unroll
        for (int ni = 0; ni < 8; ni++) {
            uint32_t* p0 = (uint32_t*)&Ps[rA * PITCH + ni * 8 + 2 * tig];
            p0[0] = f2tf32(sc[ni][0]); p0[1] = f2tf32(sc[ni][1]);
            uint32_t* p1 = (uint32_t*)&Ps[(rA + 8) * PITCH + ni * 8 + 2 * tig];
            p1[0] = f2tf32(sc[ni][2]); p1[1] = f2tf32(sc[ni][3]);
        }
        __syncwarp();

        #pragma unroll
        for (int s = 0; s < 8; s++) {
            uint32_t pa[4];
            pa[0] = __float_as_uint(Ps[rA * PITCH + 8 * s + tig]);
            pa[1] = __float_as_uint(Ps[(rA + 8) * PITCH + 8 * s + tig]);
            pa[2] = __float_as_uint(Ps[rA * PITCH + 8 * s + tig + 4]);
            pa[3] = __float_as_uint(Ps[(rA + 8) * PITCH + 8 * s + tig + 4]);
            #pragma unroll
            for (int ni = 0; ni < 8; ni++) {
                uint32_t b0 = __float_as_uint(Vs[(8 * s + tig) * PITCH + ni * 8 + gID]);
                uint32_t b1 = __float_as_uint(Vs[(8 * s + tig + 4) * PITCH + ni * 8 + gID]);
                mma_tf32(of[ni], pa, b0, b1);
            }
        }
        __syncwarp();
    }

    float inv0 = 1.0f / l0, inv1 = 1.0f / l1;
    size_t row0 = (size_t)(b * SS + q0 + rA);
    #pragma unroll
    for (int ni = 0; ni < 8; ni++) {
        int d = h * DHH + ni * 8 + 2 * tig;
        *(uint32_t*)&out[row0 * DD + d]       = pack_bf2(of[ni][0] * inv0, of[ni][1] * inv0);
        *(uint32_t*)&out[(row0 + 8) * DD + d] = pack_bf2(of[ni][2] * inv1, of[ni][3] * inv1);
    }
}

// ---------------------------------------------------------------------------
// LayerNorm: one block per row. BF16OUT when the output feeds a GEMM.
// ---------------------------------------------------------------------------
template<bool BF16OUT>
__global__ void __launch_bounds__(256) ln_kernel(
    const float* __restrict__ x, const float* __restrict__ w,
    const float* __restrict__ b, void* __restrict__ outv)
{
    int row = blockIdx.x;
    int tid = threadIdx.x;
    const float4* xr = (const float4*)(x + (size_t)row * DD);
    float4 v = xr[tid];

    __shared__ float red[8];
    float s = v.x + v.y + v.z + v.w;
    #pragma unroll
    for (int o = 16; o > 0; o >>= 1) s += __shfl_xor_sync(0xffffffffu, s, o);
    if ((tid & 31) == 0) red[tid >> 5] = s;
    __syncthreads();
    __shared__ float s_mean, s_rstd;
    if (tid == 0) {
        float t = 0.f;
        #pragma unroll
        for (int i = 0; i < 8; i++) t += red[i];
        s_mean = t * (1.0f / DD);
    }
    __syncthreads();
    float mean = s_mean;
    float d0 = v.x - mean, d1 = v.y - mean, d2 = v.z - mean, d3 = v.w - mean;
    float sq = d0*d0 + d1*d1 + d2*d2 + d3*d3;
    #pragma unroll
    for (int o = 16; o > 0; o >>= 1) sq += __shfl_xor_sync(0xffffffffu, sq, o);
    __syncthreads();
    if ((tid & 31) == 0) red[tid >> 5] = sq;
    __syncthreads();
    if (tid == 0) {
        float t = 0.f;
        #pragma unroll
        for (int i = 0; i < 8; i++) t += red[i];
        s_rstd = rsqrtf(t * (1.0f / DD) + 1e-5f);
    }
    __syncthreads();
    float rstd = s_rstd;
    float4 wv = ((const float4*)w)[tid];
    float4 bv = ((const float4*)b)[tid];
    float o0 = d0 * rstd * wv.x + bv.x;
    float o1 = d1 * rstd * wv.y + bv.y;
    float o2 = d2 * rstd * wv.z + bv.z;
    float o3 = d3 * rstd * wv.w + bv.w;
    if (BF16OUT) {
        bf16* out = (bf16*)outv;
        uint2 o4 = make_uint2(pack_bf2(o0, o1), pack_bf2(o2, o3));
        *(uint2*)(out + (size_t)row * DD + tid * 4) = o4;
    } else {
        float* out = (float*)outv;
        ((float4*)(out + (size_t)row * DD))[tid] = make_float4(o0, o1, o2, o3);
    }
}

// ---------------------------------------------------------------------------
// INL integrator: elementwise, 5 unrolled steps (DT=0.1, TARGET=0)
// ---------------------------------------------------------------------------
__global__ void __launch_bounds__(256) integrate_kernel(
    const float* __restrict__ xs0, const float* __restrict__ u,
    const float* __restrict__ al, const float* __restrict__ be,
    const float* __restrict__ gg, const float* __restrict__ x1,
    float* __restrict__ x2)
{
    int i = blockIdx.x * blockDim.x + threadIdx.x;
    float4 xs = ((const float4*)xs0)[i];
    float4 uu = ((const float4*)u)[i];
    float4 aa = ((const float4*)al)[i];
    float4 bb = ((const float4*)be)[i];
    float4 g4 = ((const float4*)gg)[i];
    float4 r1 = ((const float4*)x1)[i];
    float4 vs = make_float4(0.f, 0.f, 0.f, 0.f);
    const float DT = 0.1f;
    #pragma unroll
    for (int t = 0; t < 5; t++) {
        vs.x += DT * (-aa.x * xs.x - bb.x * vs.x + uu.x);  xs.x += DT * g4.x * vs.x;
        vs.y += DT * (-aa.y * xs.y - bb.y * vs.y + uu.y);  xs.y += DT * g4.y * vs.y;
        vs.z += DT * (-aa.z * xs.z - bb.z * vs.z + uu.z);  xs.z += DT * g4.z * vs.z;
        vs.w += DT * (-aa.w * xs.w - bb.w * vs.w + uu.w);  xs.w += DT * g4.w * vs.w;
    }
    float4 o4 = make_float4(r1.x + xs.x, r1.y + xs.y, r1.z + xs.z, r1.w + xs.w);
    ((float4*)x2)[i] = o4;
}

// ---------------------------------------------------------------------------
// Host launcher
// ---------------------------------------------------------------------------
extern "C" void kernel_launch(void* const* d_in, const int* in_sizes, int n_in,
                              void* d_out, int out_size)
{
    const float* x          = (const float*)d_in[0];
    const float* ln_attn_w  = (const float*)d_in[1];
    const float* ln_attn_b  = (const float*)d_in[2];
    const float* attn_in_w  = (const float*)d_in[3];
    const float* attn_in_b  = (const float*)d_in[4];
    const float* attn_out_w = (const float*)d_in[5];
    const float* attn_out_b = (const float*)d_in[6];
    const float* ln1_w      = (const float*)d_in[7];
    const float* ln1_b      = (const float*)d_in[8];
    const float* ln2_w      = (const float*)d_in[9];
    const float* ln2_b      = (const float*)d_in[10];
    const float* inl_u_w    = (const float*)d_in[11];
    const float* inl_u_b    = (const float*)d_in[12];
    const float* inl_a_w    = (const float*)d_in[13];
    const float* inl_a_b    = (const float*)d_in[14];
    const float* inl_b_w    = (const float*)d_in[15];
    const float* inl_b_b    = (const float*)d_in[16];
    const float* inl_g_w    = (const float*)d_in[17];
    const float* inl_g_b    = (const float*)d_in[18];
    const float* ff1_w      = (const float*)d_in[19];
    const float* ff1_b      = (const float*)d_in[20];
    const float* ff2_w      = (const float*)d_in[21];
    const float* ff2_b      = (const float*)d_in[22];
    float* out = (float*)d_out;

    float *p_qkv, *p_x1, *p_xs, *p_u, *p_al, *p_be, *p_gg, *p_x2;
    bf16 *p_ln, *p_att, *p_ctx, *p_ff;
    bf16 *w_qkv, *w_out, *w_u, *w_a, *w_b, *w_g, *w_f1, *w_f2;
    cudaGetSymbolAddress((void**)&p_ln,  g_ln);
    cudaGetSymbolAddress((void**)&p_qkv, g_qkv);
    cudaGetSymbolAddress((void**)&p_att, g_att);
    cudaGetSymbolAddress((void**)&p_ctx, g_ctx);
    cudaGetSymbolAddress((void**)&p_x1,  g_x1);
    cudaGetSymbolAddress((void**)&p_xs,  g_xs);
    cudaGetSymbolAddress((void**)&p_u,   g_u);
    cudaGetSymbolAddress((void**)&p_al,  g_al);
    cudaGetSymbolAddress((void**)&p_be,  g_be);
    cudaGetSymbolAddress((void**)&p_gg,  g_gg);
    cudaGetSymbolAddress((void**)&p_x2,  g_x2);
    cudaGetSymbolAddress((void**)&p_ff,  g_ff);
    cudaGetSymbolAddress((void**)&w_qkv, g_w_qkv);
    cudaGetSymbolAddress((void**)&w_out, g_w_out);
    cudaGetSymbolAddress((void**)&w_u,   g_w_u);
    cudaGetSymbolAddress((void**)&w_a,   g_w_a);
    cudaGetSymbolAddress((void**)&w_b,   g_w_b);
    cudaGetSymbolAddress((void**)&w_g,   g_w_g);
    cudaGetSymbolAddress((void**)&w_f1,  g_w_f1);
    cudaGetSymbolAddress((void**)&w_f2,  g_w_f2);

    cudaFuncSetAttribute((const void*)gemm_tc<0,false,true>,  cudaFuncAttributeMaxDynamicSharedMemorySize, GEMM_SMEM);
    cudaFuncSetAttribute((const void*)gemm_tc<1,true,false>,  cudaFuncAttributeMaxDynamicSharedMemorySize, GEMM_SMEM);
    cudaFuncSetAttribute((const void*)gemm_tc<4,false,false>, cudaFuncAttributeMaxDynamicSharedMemorySize, GEMM_SMEM);
    cudaFuncSetAttribute((const void*)gemm_tc<5,true,false>,  cudaFuncAttributeMaxDynamicSharedMemorySize, GEMM_SMEM);
    cudaFuncSetAttribute((const void*)gemm_inl,               cudaFuncAttributeMaxDynamicSharedMemorySize, GEMM_SMEM);
    cudaFuncSetAttribute((const void*)attn_tc_kernel,         cudaFuncAttributeMaxDynamicSharedMemorySize, ATT_SMEM);

    // 0. Pre-round all weights to bf16 (single launch)
    cvt_all_kernel<<<16 * USEG / 256, 256>>>(
        attn_in_w, attn_out_w, inl_u_w, inl_a_w, inl_b_w, inl_g_w, ff1_w, ff2_w,
        w_qkv, w_out, w_u, w_a, w_b, w_g, w_f1, w_f2);

    // 1. ln_attn(x) -> g_ln (bf16)
    ln_kernel<true><<<MM, 256>>>(x, ln_attn_w, ln_attn_b, p_ln);
    // 2. qkv = g_ln @ w_qkv^T + b  (fp32 bits, tf32-rounded, feeds attention)
    gemm_tc<0,false,true><<<dim3(3 * DD / 128, MM / 128), 128, GEMM_SMEM>>>(
        p_ln, w_qkv, attn_in_b, p_qkv, nullptr, nullptr, MM, 3 * DD, DD);
    // 3. causal MHA -> g_att (bf16)
    attn_tc_kernel<<<dim3(SS / 64, BB * HH), 128, ATT_SMEM>>>(p_qkv, p_att);
    // 4. ctx(bf16) = g_att @ w_out^T + b ; x1(fp32) = x + ctx
    gemm_tc<5,true,false><<<dim3(DD / 128, MM / 128), 128, GEMM_SMEM>>>(
        p_att, w_out, attn_out_b, p_ctx, p_x1, x, MM, DD, DD);
    // 5. xs = ln1(x1) (fp32, integrator input)
    ln_kernel<false><<<MM, 256>>>(p_x1, ln1_w, ln1_b, p_xs);
    // 6. INL controllers from ctx (batched: z=0..3)
    gemm_inl<<<dim3(DD / 128, MM / 128, 4), 128, GEMM_SMEM>>>(
        p_ctx, w_u, w_a, w_b, w_g,
        inl_u_b, inl_a_b, inl_b_b, inl_g_b,
        p_u, p_al, p_be, p_gg, MM, DD, DD);
    // 7. integrate -> x2 = x1 + xs_final
    integrate_kernel<<<(MM * DD / 4) / 256, 256>>>(p_xs, p_u, p_al, p_be, p_gg, p_x1, p_x2);
    // 8. ln2(x2) -> g_ln (bf16)
    ln_kernel<true><<<MM, 256>>>(p_x2, ln2_w, ln2_b, p_ln);
    // 9. ff1 + exact GELU -> g_ff (bf16)
    gemm_tc<1,true,false><<<dim3(FFD / 128, MM / 128), 128, GEMM_SMEM>>>(
        p_ln, w_f1, ff1_b, p_ff, nullptr, nullptr, MM, FFD, DD);
    // 10. out = g_ff @ w_f2^T + b + x2
    gemm_tc<4,false,false><<<dim3(DD / 128, MM / 128), 128, GEMM_SMEM>>>(
        p_ff, w_f2, ff2_b, out, nullptr, p_x2, MM, DD, FFD);
}

// round 16
// speedup vs baseline: 1.0142x; 1.0059x over previous
#include <cuda_runtime.h>
#include <cuda_bf16.h>
#include <cstdint>
#include <math.h>

// Problem constants
#define BB   4
#define SS   2048
#define DD   1024
#define HH   16
#define DHH  64
#define FFD  4096
#define MM   (BB*SS)      // 8192 rows

typedef __nv_bfloat16 bf16;

// ---------------------------------------------------------------------------
// Scratch (static __device__ — no allocations allowed)
// ---------------------------------------------------------------------------
__device__ bf16  g_ln [MM*DD];
__device__ float g_qkv[MM*3*DD];     // fp32 bits, tf32-rounded (attention input)
__device__ bf16  g_att[MM*DD];
__device__ bf16  g_ctx[MM*DD];
__device__ float g_x1 [MM*DD];
__device__ float g_xs [MM*DD];
__device__ float g_u  [MM*DD];
__device__ float g_al [MM*DD];
__device__ float g_be [MM*DD];
__device__ float g_gg [MM*DD];
__device__ float g_x2 [MM*DD];
__device__ bf16  g_ff [MM*FFD];
// Pre-converted bf16 weights
__device__ bf16 g_w_qkv[3*DD*DD];
__device__ bf16 g_w_out[DD*DD];
__device__ bf16 g_w_u [DD*DD];
__device__ bf16 g_w_a [DD*DD];
__device__ bf16 g_w_b [DD*DD];
__device__ bf16 g_w_g [DD*DD];
__device__ bf16 g_w_f1[FFD*DD];
__device__ bf16 g_w_f2[DD*FFD];

// ---------------------------------------------------------------------------
// Helpers
// ---------------------------------------------------------------------------
__device__ __forceinline__ uint32_t smem_u32(const void* p) {
    uint32_t a;
    asm("{ .reg .u64 t; cvta.to.shared.u64 t, %1; cvt.u32.u64 %0, t; }" : "=r"(a) : "l"(p));
    return a;
}
__device__ __forceinline__ uint32_t f2tf32(float f) {
    uint32_t u;
    asm("cvt.rna.tf32.f32 %0, %1;" : "=r"(u) : "f"(f));
    return u;
}
__device__ __forceinline__ uint32_t pack_bf2(float lo, float hi) {
    __nv_bfloat162 h = __floats2bfloat162_rn(lo, hi);
    return *reinterpret_cast<uint32_t*>(&h);
}
__device__ __forceinline__ uint32_t lds_u32(uint32_t addr) {
    uint32_t v;
    asm volatile("ld.shared.b32 %0, [%1];" : "=r"(v) : "r"(addr));
    return v;
}
__device__ __forceinline__ void cp16(uint32_t dst, const void* src) {
    asm volatile("cp.async.cg.shared.global [%0], [%1], 16;" :: "r"(dst), "l"(src));
}
#define CP_COMMIT() asm volatile("cp.async.commit_group;" ::: "memory")
__device__ __forceinline__ void cp_wait2() { asm volatile("cp.async.wait_group 2;" ::: "memory"); }
__device__ __forceinline__ void cp_wait1() { asm volatile("cp.async.wait_group 1;" ::: "memory"); }
__device__ __forceinline__ void cp_wait0() { asm volatile("cp.async.wait_group 0;" ::: "memory"); }
#define SWZ128(off) ((off) ^ (((off) >> 3) & 0x70))

__device__ __forceinline__ void mma_bf16(float* c, const uint32_t* a, uint32_t b0, uint32_t b1) {
    asm volatile("mma.sync.aligned.m16n8k16.row.col.f32.bf16.bf16.f32 "
        "{%0,%1,%2,%3}, {%4,%5,%6,%7}, {%8,%9}, {%0,%1,%2,%3};"
        : "+f"(c[0]), "+f"(c[1]), "+f"(c[2]), "+f"(c[3])
        : "r"(a[0]), "r"(a[1]), "r"(a[2]), "r"(a[3]), "r"(b0), "r"(b1));
}
__device__ __forceinline__ void mma_tf32(float* c, const uint32_t* a, uint32_t b0, uint32_t b1) {
    asm volatile("mma.sync.aligned.m16n8k8.row.col.f32.tf32.tf32.f32 "
        "{%0,%1,%2,%3}, {%4,%5,%6,%7}, {%8,%9}, {%0,%1,%2,%3};"
        : "+f"(c[0]), "+f"(c[1]), "+f"(c[2]), "+f"(c[3])
        : "r"(a[0]), "r"(a[1]), "r"(a[2]), "r"(a[3]), "r"(b0), "r"(b1));
}

// ---------------------------------------------------------------------------
// Fused fp32->bf16 conversion of all 8 weight tensors (one launch).
// ---------------------------------------------------------------------------
#define USEG (DD*DD/8)
__global__ void __launch_bounds__(256) cvt_all_kernel(
    const float* __restrict__ s_qkv, const float* __restrict__ s_out,
    const float* __restrict__ s_u,   const float* __restrict__ s_a,
    const float* __restrict__ s_b,   const float* __restrict__ s_g,
    const float* __restrict__ s_f1,  const float* __restrict__ s_f2,
    bf16* d_qkv, bf16* d_out, bf16* d_u, bf16* d_a,
    bf16* d_b, bf16* d_g, bf16* d_f1, bf16* d_f2)
{
    int i = blockIdx.x * blockDim.x + threadIdx.x;
    const float* src; bf16* dst; int off;
    if      (i <  3 * USEG) { src = s_qkv; dst = d_qkv; off = i; }
    else if (i <  4 * USEG) { src = s_out; dst = d_out; off = i -  3 * USEG; }
    else if (i <  5 * USEG) { src = s_u;   dst = d_u;   off = i -  4 * USEG; }
    else if (i <  6 * USEG) { src = s_a;   dst = d_a;   off = i -  5 * USEG; }
    else if (i <  7 * USEG) { src = s_b;   dst = d_b;   off = i -  6 * USEG; }
    else if (i <  8 * USEG) { src = s_g;   dst = d_g;   off = i -  7 * USEG; }
    else if (i < 12 * USEG) { src = s_f1;  dst = d_f1;  off = i -  8 * USEG; }
    else                    { src = s_f2;  dst = d_f2;  off = i - 12 * USEG; }
    float4 v0 = ((const float4*)src)[2 * off];
    float4 v1 = ((const float4*)src)[2 * off + 1];
    uint4 o;
    o.x = pack_bf2(v0.x, v0.y);
    o.y = pack_bf2(v0.z, v0.w);
    o.z = pack_bf2(v1.x, v1.y);
    o.w = pack_bf2(v1.z, v1.w);
    ((uint4*)dst)[off] = o;
}

// ---------------------------------------------------------------------------
// Shared bf16 GEMM mainloop (proven scalar-LDS fragment loads).
// ---------------------------------------------------------------------------
#define STAGE_BYTES 32768
#define NSTAGE 3
#define GEMM_SMEM   (NSTAGE * STAGE_BYTES + 1024)

__device__ __forceinline__ void bf16_mainloop(
    const bf16* __restrict__ Abase, const bf16* __restrict__ Wbase,
    int K, uint32_t base, float acc[4][8][4])
{
    const int tid = threadIdx.x;
    const int lane = tid & 31;
    const int wid = tid >> 5;
    const int gID = lane >> 2, tig = lane & 3;
    const int wm = (wid & 1) * 64;
    const int wn = (wid >> 1) * 64;

    const uint32_t gOff0 = (uint32_t)((tid >> 3) * K + (tid & 7) * 8);
    const uint32_t gStep = (uint32_t)(16 * K);
    const uint32_t sOff0 = SWZ128((uint32_t)((tid >> 3) * 128 + (tid & 7) * 16));

    const uint32_t rowA0 = (uint32_t)((wm + gID) * 128);
    const uint32_t rowB0 = (uint32_t)((wn + gID) * 128);
    const uint32_t xmask = (uint32_t)(gID << 4);

    const int niter = K / 64;

    #pragma unroll
    for (int p = 0; p < 2; p++) {
        uint32_t st = base + p * STAGE_BYTES;
        const bf16* As = Abase + p * 64;
        const bf16* Ws = Wbase + p * 64;
        #pragma unroll
        for (int i = 0; i < 8; i++) cp16(st + sOff0 + i * 2048, As + gOff0 + i * gStep);
        #pragma unroll
        for (int i = 0; i < 8; i++) cp16(st + 16384 + sOff0 + i * 2048, Ws + gOff0 + i * gStep);
        CP_COMMIT();
    }

    int stage = 0;
    for (int it = 0; it < niter; it++) {
        if (it + 1 < niter) cp_wait1(); else cp_wait0();
        __syncthreads();

        if (it + 2 < niter) {
            int ns = stage + 2; if (ns >= NSTAGE) ns -= NSTAGE;
            uint32_t st = base + ns * STAGE_BYTES;
            const bf16* As = Abase + (it + 2) * 64;
            const bf16* Ws = Wbase + (it + 2) * 64;
            #pragma unroll
            for (int i = 0; i < 8; i++) cp16(st + sOff0 + i * 2048, As + gOff0 + i * gStep);
            #pragma unroll
            for (int i = 0; i < 8; i++) cp16(st + 16384 + sOff0 + i * 2048, Ws + gOff0 + i * gStep);
            CP_COMMIT();
        }

        uint32_t sA = base + stage * STAGE_BYTES;
        uint32_t sB = sA + 16384;

        uint32_t af[2][4][4];
        uint32_t bfr[2][8][2];
        {
            uint32_t x0 = ((uint32_t)(tig * 4)) ^ xmask;
            uint32_t x1 = x0 ^ 16u;
            #pragma unroll
            for (int mi = 0; mi < 4; mi++) {
                af[0][mi][0] = lds_u32(sA + rowA0 + mi * 2048 + x0);
                af[0][mi][1] = lds_u32(sA + rowA0 + mi * 2048 + 1024 + x0);
                af[0][mi][2] = lds_u32(sA + rowA0 + mi * 2048 + x1);
                af[0][mi][3] = lds_u32(sA + rowA0 + mi * 2048 + 1024 + x1);
            }
            #pragma unroll
            for (int ni = 0; ni < 8; ni++) {
                bfr[0][ni][0] = lds_u32(sB + rowB0 + ni * 1024 + x0);
                bfr[0][ni][1] = lds_u32(sB + rowB0 + ni * 1024 + x1);
            }
        }
        #pragma unroll
        for (int s = 0; s < 4; s++) {
            int cur = s & 1, nxt = cur ^ 1;
            if (s < 3) {
                uint32_t x0 = ((uint32_t)((s + 1) * 32 + tig * 4)) ^ xmask;
                uint32_t x1 = x0 ^ 16u;
                #pragma unroll
                for (int mi = 0; mi < 4; mi++) {
                    af[nxt][mi][0] = lds_u32(sA + rowA0 + mi * 2048 + x0);
                    af[nxt][mi][1] = lds_u32(sA + rowA0 + mi * 2048 + 1024 + x0);
                    af[nxt][mi][2] = lds_u32(sA + rowA0 + mi * 2048 + x1);
                    af[nxt][mi][3] = lds_u32(sA + rowA0 + mi * 2048 + 1024 + x1);
                }
                #pragma unroll
                for (int ni = 0; ni < 8; ni++) {
                    bfr[nxt][ni][0] = lds_u32(sB + rowB0 + ni * 1024 + x0);
                    bfr[nxt][ni][1] = lds_u32(sB + rowB0 + ni * 1024 + x1);
                }
            }
            #pragma unroll
            for (int ni = 0; ni < 8; ni++)
                #pragma unroll
                for (int mi = 0; mi < 4; mi++)
                    mma_bf16(acc[mi][ni], af[cur][mi], bfr[cur][ni][0], bfr[cur][ni][1]);
        }

        stage++; if (stage >= NSTAGE) stage = 0;
    }
}

// ---------------------------------------------------------------------------
// Standard GEMM kernel with templated epilogue.
// EPI: 0=none 1=gelu 2=sigmoid 3=softplus 4=C=v+res 5=dual(Cb16=v, C2=v+res)
// CB16: C stored bf16.  RT32: C stored fp32 but tf32-rounded (feeds attention).
// ---------------------------------------------------------------------------
template<int EPI, bool CB16, bool RT32>
__global__ void __launch_bounds__(128, 2) gemm_tc(
    const bf16* __restrict__ A, const bf16* __restrict__ W,
    const float* __restrict__ bias, void* __restrict__ Cv,
    float* __restrict__ C2, const float* __restrict__ res,
    int M, int N, int K)
{
    extern __shared__ char dsm[];
    uint32_t raw = smem_u32(dsm);
    uint32_t base = (raw + 1023u) & ~1023u;

    float acc[4][8][4];
    #pragma unroll
    for (int mi = 0; mi < 4; mi++)
        #pragma unroll
        for (int ni = 0; ni < 8; ni++)
            #pragma unroll
            for (int j = 0; j < 4; j++) acc[mi][ni][j] = 0.f;

    bf16_mainloop(A + (size_t)(blockIdx.y * 128) * K,
                  W + (size_t)(blockIdx.x * 128) * K, K, base, acc);

    int tid = threadIdx.x;
    int wid = tid >> 5, lane = tid & 31;
    int gID = lane >> 2, tig = lane & 3;
    float* Cf = (float*)Cv;
    bf16*  Cb = (bf16*)Cv;
    int row0 = blockIdx.y * 128 + (wid & 1) * 64 + gID;
    int col0 = blockIdx.x * 128 + (wid >> 1) * 64;
    #pragma unroll
    for (int mi = 0; mi < 4; mi++) {
        #pragma unroll
        for (int half = 0; half < 2; half++) {
            int r = row0 + mi * 16 + half * 8;
            size_t rbase = (size_t)r * N;
            #pragma unroll
            for (int ni = 0; ni < 8; ni++) {
                int c = col0 + ni * 8 + 2 * tig;
                float v0 = acc[mi][ni][half * 2 + 0] + bias[c];
                float v1 = acc[mi][ni][half * 2 + 1] + bias[c + 1];
                if (EPI == 1) {
                    v0 = 0.5f * v0 * (1.0f + erff(v0 * 0.70710678118654752f));
                    v1 = 0.5f * v1 * (1.0f + erff(v1 * 0.70710678118654752f));
                } else if (EPI == 2) {
                    v0 = 1.0f / (1.0f + expf(-v0));
                    v1 = 1.0f / (1.0f + expf(-v1));
                } else if (EPI == 3) {
                    v0 = (v0 > 0.f) ? (v0 + log1pf(expf(-v0))) : log1pf(expf(v0));
                    v1 = (v1 > 0.f) ? (v1 + log1pf(expf(-v1))) : log1pf(expf(v1));
                }
                if (EPI == 4) {
                    float2 r2 = *(const float2*)(res + rbase + c);
                    *(float2*)(Cf + rbase + c) = make_float2(v0 + r2.x, v1 + r2.y);
                } else if (EPI == 5) {
                    float2 r2 = *(const float2*)(res + rbase + c);
                    *(uint32_t*)(Cb + rbase + c) = pack_bf2(v0, v1);
                    *(float2*)(C2 + rbase + c) = make_float2(v0 + r2.x, v1 + r2.y);
                } else if (CB16) {
                    *(uint32_t*)(Cb + rbase + c) = pack_bf2(v0, v1);
                } else if (RT32) {
                    *(float2*)(Cf + rbase + c) = make_float2(
                        __uint_as_float(f2tf32(v0)), __uint_as_float(f2tf32(v1)));
                } else {
                    *(float2*)(Cf + rbase + c) = make_float2(v0, v1);
                }
            }
        }
    }
}

// ---------------------------------------------------------------------------
// Batched INL controller GEMM: blockIdx.z selects weight/bias/output/act.
// ---------------------------------------------------------------------------
__global__ void __launch_bounds__(128, 2) gemm_inl(
    const bf16* __restrict__ A,
    const bf16* __restrict__ W0, const bf16* __restrict__ W1,
    const bf16* __restrict__ W2, const bf16* __restrict__ W3,
    const float* __restrict__ b0, const float* __restrict__ b1,
    const float* __restrict__ b2, const float* __restrict__ b3,
    float* __restrict__ C0, float* __restrict__ C1,
    float* __restrict__ C2o, float* __restrict__ C3,
    int M, int N, int K)
{
    extern __shared__ char dsm[];
    uint32_t raw = smem_u32(dsm);
    uint32_t base = (raw + 1023u) & ~1023u;

    int z = blockIdx.z;
    const bf16*  W    = (z == 0) ? W0 : (z == 1) ? W1 : (z == 2) ? W2 : W3;
    const float* bias = (z == 0) ? b0 : (z == 1) ? b1 : (z == 2) ? b2 : b3;
    float*       C    = (z == 0) ? C0 : (z == 1) ? C1 : (z == 2) ? C2o : C3;

    float acc[4][8][4];
    #pragma unroll
    for (int mi = 0; mi < 4; mi++)
        #pragma unroll
        for (int ni = 0; ni < 8; ni++)
            #pragma unroll
            for (int j = 0; j < 4; j++) acc[mi][ni][j] = 0.f;

    bf16_mainloop(A + (size_t)(blockIdx.y * 128) * K,
                  W + (size_t)(blockIdx.x * 128) * K, K, base, acc);

    int tid = threadIdx.x;
    int wid = tid >> 5, lane = tid & 31;
    int gID = lane >> 2, tig = lane & 3;
    int row0 = blockIdx.y * 128 + (wid & 1) * 64 + gID;
    int col0 = blockIdx.x * 128 + (wid >> 1) * 64;
    #pragma unroll
    for (int mi = 0; mi < 4; mi++) {
        #pragma unroll
        for (int half = 0; half < 2; half++) {
            int r = row0 + mi * 16 + half * 8;
            size_t rbase = (size_t)r * N;
            #pragma unroll
            for (int ni = 0; ni < 8; ni++) {
                int c = col0 + ni * 8 + 2 * tig;
                float v0 = acc[mi][ni][half * 2 + 0] + bias[c];
                float v1 = acc[mi][ni][half * 2 + 1] + bias[c + 1];
                if (z == 2) {
                    v0 = (v0 > 0.f) ? (v0 + log1pf(expf(-v0))) : log1pf(expf(v0));
                    v1 = (v1 > 0.f) ? (v1 + log1pf(expf(-v1))) : log1pf(expf(v1));
                } else if (z != 0) {
                    v0 = 1.0f / (1.0f + expf(-v0));
                    v1 = 1.0f / (1.0f + expf(-v1));
                }
                *(float2*)(C + rbase + c) = make_float2(v0, v1);
            }
        }
    }
}

// ---------------------------------------------------------------------------
// Tensor-core causal flash attention with split-buffer K/V pipeline.
// Smem: K0, K1, V, P — 4 * 18KB = 72KB (3 CTAs/SM preserved).
// K double-buffered (hidden behind full tile); V single-buffered (hidden
// behind S-mma + softmax). qkv already tf32-rounded; Q scale 2^-3 exact.
// Longest Q-tiles first. Softmax uses __expf.
// ---------------------------------------------------------------------------
#define PITCH 72
#define KVT (64 * PITCH)
#define ATT_SMEM (4 * KVT * 4)

__global__ void __launch_bounds__(128) attn_tc_kernel(
    const float* __restrict__ qkv, bf16* __restrict__ out)
{
    extern __shared__ float sm[];
    float* K0 = sm;
    float* K1 = sm + KVT;
    float* Vs = sm + 2 * KVT;
    float* Ps = sm + 3 * KVT;
    uint32_t k0b = smem_u32(K0);
    uint32_t k1b = smem_u32(K1);
    uint32_t vsb = smem_u32(Vs);

    int tid = threadIdx.x;
    int wid = tid >> 5, lane = tid & 31;
    int gID = lane >> 2, tig = lane & 3;
    int b = blockIdx.y >> 4, h = blockIdx.y & 15;
    // Longest-first scheduling
    int qb = (int)gridDim.x - 1 - (int)blockIdx.x;
    int q0 = qb * 64;
    const float scale = 0.125f;

    // Per-thread K/V staging offsets (row = f>>4, col = (f&15)*4)
    uint32_t kvso[8];
    size_t   kvgo[8];
    #pragma unroll
    for (int i = 0; i < 8; i++) {
        int f = tid + i * 128;
        int r = f >> 4;
        int c = (f & 15) * 4;
        kvso[i] = (uint32_t)((r * PITCH + c) * 4);
        kvgo[i] = (size_t)(b * SS + r) * (3 * DD) + h * DHH + c;
    }

    int nt = qb + 1;
    // Prologue: issue K(0) into K0
    #pragma unroll
    for (int i = 0; i < 8; i++) cp16(k0b + kvso[i], qkv + kvgo[i] + DD);
    CP_COMMIT();

    // Load Q tile (already tf32-rounded; *2^-3 exact) into Ps staging
    #pragma unroll
    for (int i = 0; i < 8; i++) {
        int f = tid + i * 128;
        int r = f >> 4;
        int c = (f & 15) * 4;
        float4 v = *(const float4*)&qkv[(size_t)(b * SS + q0 + r) * (3 * DD) + h * DHH + c];
        *(float4*)&Ps[r * PITCH + c] =
            make_float4(v.x * scale, v.y * scale, v.z * scale, v.w * scale);
    }
    __syncthreads();

    int rA = wid * 16 + gID;
    uint32_t qf[8][4];
    #pragma unroll
    for (int s = 0; s < 8; s++) {
        qf[s][0] = __float_as_uint(Ps[rA * PITCH + 8 * s + tig]);
        qf[s][1] = __float_as_uint(Ps[(rA + 8) * PITCH + 8 * s + tig]);
        qf[s][2] = __float_as_uint(Ps[rA * PITCH + 8 * s + tig + 4]);
        qf[s][3] = __float_as_uint(Ps[(rA + 8) * PITCH + 8 * s + tig + 4]);
    }

    float of[8][4];
    #pragma unroll
    for (int ni = 0; ni < 8; ni++)
        #pragma unroll
        for (int j = 0; j < 4; j++) of[ni][j] = 0.f;
    float m0 = -1e30f, m1 = -1e30f, l0 = 0.f, l1 = 0.f;

    for (int jt = 0; jt < nt; jt++) {
        bool pf = (jt + 1 < nt);
        // Guard: V overwrite (prior PV done), K(jt+1) buffer free, Ps free
        __syncthreads();
        // Issue V(jt)
        {
            size_t koff = (size_t)(jt * 64) * (3 * DD);
            #pragma unroll
            for (int i = 0; i < 8; i++)
                cp16(vsb + kvso[i], qkv + kvgo[i] + koff + 2 * DD);
            CP_COMMIT();
        }
        // Issue K(jt+1) into alternate K buffer
        if (pf) {
            uint32_t dst = ((jt + 1) & 1) ? k1b : k0b;
            size_t koff = (size_t)((jt + 1) * 64) * (3 * DD);
            #pragma unroll
            for (int i = 0; i < 8; i++)
                cp16(dst + kvso[i], qkv + kvgo[i] + koff + DD);
            CP_COMMIT();
        }
        // K(jt) arrived (committed a full tile ago)
        if (pf) cp_wait2(); else cp_wait1();
        __syncthreads();

        const float* Ks = (jt & 1) ? K1 : K0;

        float sc[8][4];
        #pragma unroll
        for (int ni = 0; ni < 8; ni++)
            #pragma unroll
            for (int j = 0; j < 4; j++) sc[ni][j] = 0.f;
        #pragma unroll
        for (int s = 0; s < 8; s++) {
            #pragma unroll
            for (int ni = 0; ni < 8; ni++) {
                uint32_t b0 = __float_as_uint(Ks[(ni * 8 + gID) * PITCH + 8 * s + tig]);
                uint32_t b1 = __float_as_uint(Ks[(ni * 8 + gID) * PITCH + 8 * s + tig + 4]);
                mma_tf32(sc[ni], qf[s], b0, b1);
            }
        }

        if (jt == nt - 1) {
            #pragma unroll
            for (int ni = 0; ni < 8; ni++) {
                int ct = ni * 8 + 2 * tig;
                if (ct > rA)         sc[ni][0] = -1e30f;
                if (ct + 1 > rA)     sc[ni][1] = -1e30f;
                if (ct > rA + 8)     sc[ni][2] = -1e30f;
                if (ct + 1 > rA + 8) sc[ni][3] = -1e30f;
            }
        }

        float mx0 = -1e30f, mx1 = -1e30f;
        #pragma unroll
        for (int ni = 0; ni < 8; ni++) {
            mx0 = fmaxf(mx0, fmaxf(sc[ni][0], sc[ni][1]));
            mx1 = fmaxf(mx1, fmaxf(sc[ni][2], sc[ni][3]));
        }
        mx0 = fmaxf(mx0, __shfl_xor_sync(0xffffffffu, mx0, 1));
        mx0 = fmaxf(mx0, __shfl_xor_sync(0xffffffffu, mx0, 2));
        mx1 = fmaxf(mx1, __shfl_xor_sync(0xffffffffu, mx1, 1));
        mx1 = fmaxf(mx1, __shfl_xor_sync(0xffffffffu, mx1, 2));
        float mn0 = fmaxf(m0, mx0), mn1 = fmaxf(m1, mx1);
        float rs0 = __expf(m0 - mn0), rs1 = __expf(m1 - mn1);
        m0 = mn0; m1 = mn1;

        float sum0 = 0.f, sum1 = 0.f;
        #pragma unroll
        for (int ni = 0; ni < 8; ni++) {
            sc[ni][0] = __expf(sc[ni][0] - mn0);
            sc[ni][1] = __expf(sc[ni][1] - mn0);
            sc[ni][2] = __expf(sc[ni][2] - mn1);
            sc[ni][3] = __expf(sc[ni][3] - mn1);
            sum0 += sc[ni][0] + sc[ni][1];
            sum1 += sc[ni][2] + sc[ni][3];
        }
        sum0 += __shfl_xor_sync(0xffffffffu, sum0, 1);
        sum0 += __shfl_xor_sync(0xffffffffu, sum0, 2);
        sum1 += __shfl_xor_sync(0xffffffffu, sum1, 1);
        sum1 += __shfl_xor_sync(0xffffffffu, sum1, 2);
        l0 = l0 * rs0 + sum0;
        l1 = l1 * rs1 + sum1;

        #pragma unroll
        for (int ni = 0; ni < 8; ni++) {
            of[ni][0] *= rs0; of[ni][1] *= rs0;
            of[ni][2] *= rs1; of[ni][3] *= rs1;
        }

        // V(jt) arrived (hidden behind S-mma + softmax)
        if (pf) cp_wait1(); else cp_wait0();
        __syncthreads();

        #pragma unroll
        for (int ni = 0; ni < 8; ni++) {
            uint32_t* p0 = (uint32_t*)&Ps[rA * PITCH + ni * 8 + 2 * tig];
            p0[0] = f2tf32(sc[ni][0]); p0[1] = f2tf32(sc[ni][1]);
            uint32_t* p1 = (uint32_t*)&Ps[(rA + 8) * PITCH + ni * 8 + 2 * tig];
            p1[0] = f2tf32(sc[ni][2]); p1[1] = f2tf32(sc[ni][3]);
        }
        __syncwarp();

        #pragma unroll
        for (int s = 0; s < 8; s++) {
            uint32_t pa[4];
            pa[0] = __float_as_uint(Ps[rA * PITCH + 8 * s + tig]);
            pa[1] = __float_as_uint(Ps[(rA + 8) * PITCH + 8 * s + tig]);
            pa[2] = __float_as_uint(Ps[rA * PITCH + 8 * s + tig + 4]);
            pa[3] = __float_as_uint(Ps[(rA + 8) * PITCH + 8 * s + tig + 4]);
            #pragma unroll
            for (int ni = 0; ni < 8; ni++) {
                uint32_t b0 = __float_as_uint(Vs[(8 * s + tig) * PITCH + ni * 8 + gID]);
                uint32_t b1 = __float_as_uint(Vs[(8 * s + tig + 4) * PITCH + ni * 8 + gID]);
                mma_tf32(of[ni], pa, b0, b1);
            }
        }
    }

    float inv0 = 1.0f / l0, inv1 = 1.0f / l1;
    size_t row0 = (size_t)(b * SS + q0 + rA);
    #pragma unroll
    for (int ni = 0; ni < 8; ni++) {
        int d = h * DHH + ni * 8 + 2 * tig;
        *(uint32_t*)&out[row0 * DD + d]       = pack_bf2(of[ni][0] * inv0, of[ni][1] * inv0);
        *(uint32_t*)&out[(row0 + 8) * DD + d] = pack_bf2(of[ni][2] * inv1, of[ni][3] * inv1);
    }
}

// ---------------------------------------------------------------------------
// LayerNorm: one block per row. BF16OUT when the output feeds a GEMM.
// ---------------------------------------------------------------------------
template<bool BF16OUT>
__global__ void __launch_bounds__(256) ln_kernel(
    const float* __restrict__ x, const float* __restrict__ w,
    const float* __restrict__ b, void* __restrict__ outv)
{
    int row = blockIdx.x;
    int tid = threadIdx.x;
    const float4* xr = (const float4*)(x + (size_t)row * DD);
    float4 v = xr[tid];

    __shared__ float red[8];
    float s = v.x + v.y + v.z + v.w;
    #pragma unroll
    for (int o = 16; o > 0; o >>= 1) s += __shfl_xor_sync(0xffffffffu, s, o);
    if ((tid & 31) == 0) red[tid >> 5] = s;
    __syncthreads();
    __shared__ float s_mean, s_rstd;
    if (tid == 0) {
        float t = 0.f;
        #pragma unroll
        for (int i = 0; i < 8; i++) t += red[i];
        s_mean = t * (1.0f / DD);
    }
    __syncthreads();
    float mean = s_mean;
    float d0 = v.x - mean, d1 = v.y - mean, d2 = v.z - mean, d3 = v.w - mean;
    float sq = d0*d0 + d1*d1 + d2*d2 + d3*d3;
    #pragma unroll
    for (int o = 16; o > 0; o >>= 1) sq += __shfl_xor_sync(0xffffffffu, sq, o);
    __syncthreads();
    if ((tid & 31) == 0) red[tid >> 5] = sq;
    __syncthreads();
    if (tid == 0) {
        float t = 0.f;
        #pragma unroll
        for (int i = 0; i < 8; i++) t += red[i];
        s_rstd = rsqrtf(t * (1.0f / DD) + 1e-5f);
    }
    __syncthreads();
    float rstd = s_rstd;
    float4 wv = ((const float4*)w)[tid];
    float4 bv = ((const float4*)b)[tid];
    float o0 = d0 * rstd * wv.x + bv.x;
    float o1 = d1 * rstd * wv.y + bv.y;
    float o2 = d2 * rstd * wv.z + bv.z;
    float o3 = d3 * rstd * wv.w + bv.w;
    if (BF16OUT) {
        bf16* out = (bf16*)outv;
        uint2 o4 = make_uint2(pack_bf2(o0, o1), pack_bf2(o2, o3));
        *(uint2*)(out + (size_t)row * DD + tid * 4) = o4;
    } else {
        float* out = (float*)outv;
        ((float4*)(out + (size_t)row * DD))[tid] = make_float4(o0, o1, o2, o3);
    }
}

// ---------------------------------------------------------------------------
// Fused INL integrator + ln2. One block per row (256 threads x 4 elems).
// Integrates (bit-identical to the old integrate_kernel), writes x2,
// then applies ln2 to the row in-register and stores bf16 for the ff1 GEMM.
// ---------------------------------------------------------------------------
__global__ void __launch_bounds__(256) integrate_ln2_kernel(
    const float* __restrict__ xs0, const float* __restrict__ u,
    const float* __restrict__ al, const float* __restrict__ be,
    const float* __restrict__ gg, const float* __restrict__ x1,
    float* __restrict__ x2,
    const float* __restrict__ lw, const float* __restrict__ lb,
    bf16* __restrict__ lnout)
{
    int row = blockIdx.x;
    int tid = threadIdx.x;
    size_t idx = (size_t)row * 256 + tid;   // float4 index; row-major rows of 1024
    float4 xs = ((const float4*)xs0)[idx];
    float4 uu = ((const float4*)u)[idx];
    float4 aa = ((const float4*)al)[idx];
    float4 bb = ((const float4*)be)[idx];
    float4 g4 = ((const float4*)gg)[idx];
    float4 r1 = ((const float4*)x1)[idx];
    float4 vs = make_float4(0.f, 0.f, 0.f, 0.f);
    const float DT = 0.1f;
    #pragma unroll
    for (int t = 0; t < 5; t++) {
        vs.x += DT * (-aa.x * xs.x - bb.x * vs.x + uu.x);  xs.x += DT * g4.x * vs.x;
        vs.y += DT * (-aa.y * xs.y - bb.y * vs.y + uu.y);  xs.y += DT * g4.y * vs.y;
        vs.z += DT * (-aa.z * xs.z - bb.z * vs.z + uu.z);  xs.z += DT * g4.z * vs.z;
        vs.w += DT * (-aa.w * xs.w - bb.w * vs.w + uu.w);  xs.w += DT * g4.w * vs.w;
    }
    float4 v = make_float4(r1.x + xs.x, r1.y + xs.y, r1.z + xs.z, r1.w + xs.w);
    ((float4*)x2)[idx] = v;

    // ln2 on v (identical reduction structure to ln_kernel)
    __shared__ float red[8];
    float s = v.x + v.y + v.z + v.w;
    #pragma unroll
    for (int o = 16; o > 0; o >>= 1) s += __shfl_xor_sync(0xffffffffu, s, o);
    if ((tid & 31) == 0) red[tid >> 5] = s;
    __syncthreads();
    __shared__ float s_mean, s_rstd;
    if (tid == 0) {
        float t = 0.f;
        #pragma unroll
        for (int i = 0; i < 8; i++) t += red[i];
        s_mean = t * (1.0f / DD);
    }
    __syncthreads();
    float mean = s_mean;
    float d0 = v.x - mean, d1 = v.y - mean, d2 = v.z - mean, d3 = v.w - mean;
    float sq = d0*d0 + d1*d1 + d2*d2 + d3*d3;
    #pragma unroll
    for (int o = 16; o > 0; o >>= 1) sq += __shfl_xor_sync(0xffffffffu, sq, o);
    __syncthreads();
    if ((tid & 31) == 0) red[tid >> 5] = sq;
    __syncthreads();
    if (tid == 0) {
        float t = 0.f;
        #pragma unroll
        for (int i = 0; i < 8; i++) t += red[i];
        s_rstd = rsqrtf(t * (1.0f / DD) + 1e-5f);
    }
    __syncthreads();
    float rstd = s_rstd;
    float4 wv = ((const float4*)lw)[tid];
    float4 bv = ((const float4*)lb)[tid];
    float o0 = d0 * rstd * wv.x + bv.x;
    float o1 = d1 * rstd * wv.y + bv.y;
    float o2 = d2 * rstd * wv.z + bv.z;
    float o3 = d3 * rstd * wv.w + bv.w;
    uint2 o4 = make_uint2(pack_bf2(o0, o1), pack_bf2(o2, o3));
    *(uint2*)(lnout + (size_t)row * DD + tid * 4) = o4;
}

// ---------------------------------------------------------------------------
// Host launcher
// ---------------------------------------------------------------------------
extern "C" void kernel_launch(void* const* d_in, const int* in_sizes, int n_in,
                              void* d_out, int out_size)
{
    const float* x          = (const float*)d_in[0];
    const float* ln_attn_w  = (const float*)d_in[1];
    const float* ln_attn_b  = (const float*)d_in[2];
    const float* attn_in_w  = (const float*)d_in[3];
    const float* attn_in_b  = (const float*)d_in[4];
    const float* attn_out_w = (const float*)d_in[5];
    const float* attn_out_b = (const float*)d_in[6];
    const float* ln1_w      = (const float*)d_in[7];
    const float* ln1_b      = (const float*)d_in[8];
    const float* ln2_w      = (const float*)d_in[9];
    const float* ln2_b      = (const float*)d_in[10];
    const float* inl_u_w    = (const float*)d_in[11];
    const float* inl_u_b    = (const float*)d_in[12];
    const float* inl_a_w    = (const float*)d_in[13];
    const float* inl_a_b    = (const float*)d_in[14];
    const float* inl_b_w    = (const float*)d_in[15];
    const float* inl_b_b    = (const float*)d_in[16];
    const float* inl_g_w    = (const float*)d_in[17];
    const float* inl_g_b    = (const float*)d_in[18];
    const float* ff1_w      = (const float*)d_in[19];
    const float* ff1_b      = (const float*)d_in[20];
    const float* ff2_w      = (const float*)d_in[21];
    const float* ff2_b      = (const float*)d_in[22];
    float* out = (float*)d_out;

    float *p_qkv, *p_x1, *p_xs, *p_u, *p_al, *p_be, *p_gg, *p_x2;
    bf16 *p_ln, *p_att, *p_ctx, *p_ff;
    bf16 *w_qkv, *w_out, *w_u, *w_a, *w_b, *w_g, *w_f1, *w_f2;
    cudaGetSymbolAddress((void**)&p_ln,  g_ln);
    cudaGetSymbolAddress((void**)&p_qkv, g_qkv);
    cudaGetSymbolAddress((void**)&p_att, g_att);
    cudaGetSymbolAddress((void**)&p_ctx, g_ctx);
    cudaGetSymbolAddress((void**)&p_x1,  g_x1);
    cudaGetSymbolAddress((void**)&p_xs,  g_xs);
    cudaGetSymbolAddress((void**)&p_u,   g_u);
    cudaGetSymbolAddress((void**)&p_al,  g_al);
    cudaGetSymbolAddress((void**)&p_be,  g_be);
    cudaGetSymbolAddress((void**)&p_gg,  g_gg);
    cudaGetSymbolAddress((void**)&p_x2,  g_x2);
    cudaGetSymbolAddress((void**)&p_ff,  g_ff);
    cudaGetSymbolAddress((void**)&w_qkv, g_w_qkv);
    cudaGetSymbolAddress((void**)&w_out, g_w_out);
    cudaGetSymbolAddress((void**)&w_u,   g_w_u);
    cudaGetSymbolAddress((void**)&w_a,   g_w_a);
    cudaGetSymbolAddress((void**)&w_b,   g_w_b);
    cudaGetSymbolAddress((void**)&w_g,   g_w_g);
    cudaGetSymbolAddress((void**)&w_f1,  g_w_f1);
    cudaGetSymbolAddress((void**)&w_f2,  g_w_f2);

    cudaFuncSetAttribute((const void*)gemm_tc<0,false,true>,  cudaFuncAttributeMaxDynamicSharedMemorySize, GEMM_SMEM);
    cudaFuncSetAttribute((const void*)gemm_tc<1,true,false>,  cudaFuncAttributeMaxDynamicSharedMemorySize, GEMM_SMEM);
    cudaFuncSetAttribute((const void*)gemm_tc<4,false,false>, cudaFuncAttributeMaxDynamicSharedMemorySize, GEMM_SMEM);
    cudaFuncSetAttribute((const void*)gemm_tc<5,true,false>,  cudaFuncAttributeMaxDynamicSharedMemorySize, GEMM_SMEM);
    cudaFuncSetAttribute((const void*)gemm_inl,               cudaFuncAttributeMaxDynamicSharedMemorySize, GEMM_SMEM);
    cudaFuncSetAttribute((const void*)attn_tc_kernel,         cudaFuncAttributeMaxDynamicSharedMemorySize, ATT_SMEM);

    // 0. Pre-round all weights to bf16 (single launch)
    cvt_all_kernel<<<16 * USEG / 256, 256>>>(
        attn_in_w, attn_out_w, inl_u_w, inl_a_w, inl_b_w, inl_g_w, ff1_w, ff2_w,
        w_qkv, w_out, w_u, w_a, w_b, w_g, w_f1, w_f2);

    // 1. ln_attn(x) -> g_ln (bf16)
    ln_kernel<true><<<MM, 256>>>(x, ln_attn_w, ln_attn_b, p_ln);
    // 2. qkv = g_ln @ w_qkv^T + b  (fp32 bits, tf32-rounded, feeds attention)
    gemm_tc<0,false,true><<<dim3(3 * DD / 128, MM / 128), 128, GEMM_SMEM>>>(
        p_ln, w_qkv, attn_in_b, p_qkv, nullptr, nullptr, MM, 3 * DD, DD);
    // 3. causal MHA -> g_att (bf16)
    attn_tc_kernel<<<dim3(SS / 64, BB * HH), 128, ATT_SMEM>>>(p_qkv, p_att);
    // 4. ctx(bf16) = g_att @ w_out^T + b ; x1(fp32) = x + ctx
    gemm_tc<5,true,false><<<dim3(DD / 128, MM / 128), 128, GEMM_SMEM>>>(
        p_att, w_out, attn_out_b, p_ctx, p_x1, x, MM, DD, DD);
    // 5. xs = ln1(x1) (fp32, integrator input)
    ln_kernel<false><<<MM, 256>>>(p_x1, ln1_w, ln1_b, p_xs);
    // 6. INL controllers from ctx (batched: z=0..3)
    gemm_inl<<<dim3(DD / 128, MM / 128, 4), 128, GEMM_SMEM>>>(
        p_ctx, w_u, w_a, w_b, w_g,
        inl_u_b, inl_a_b, inl_b_b, inl_g_b,
        p_u, p_al, p_be, p_gg, MM, DD, DD);
    // 7+8. integrate -> x2 = x1 + xs_final, fused with ln2(x2) -> g_ln (bf16)
    integrate_ln2_kernel<<<MM, 256>>>(p_xs, p_u, p_al, p_be, p_gg, p_x1,
                                      p_x2, ln2_w, ln2_b, p_ln);
    // 9. ff1 + exact GELU -> g_ff (bf16)
    gemm_tc<1,true,false><<<dim3(FFD / 128, MM / 128), 128, GEMM_SMEM>>>(
        p_ln, w_f1, ff1_b, p_ff, nullptr, nullptr, MM, FFD, DD);
    // 10. out = g_ff @ w_f2^T + b + x2
    gemm_tc<4,false,false><<<dim3(DD / 128, MM / 128), 128, GEMM_SMEM>>>(
        p_ff, w_f2, ff2_b, out, nullptr, p_x2, MM, DD, FFD);
}